// round 7
// baseline (speedup 1.0000x reference)
#include <cuda_runtime.h>
#include <cuda_bf16.h>
#include <math.h>

// ---------------------------------------------------------------------------
// Problem constants (B=1, S=2048, D=4096, n_head=32, kv_head=8, hd=128)
// ---------------------------------------------------------------------------
#define S_LEN 2048
#define D_MODEL 4096
#define GS_DIM 1024
#define N_HEAD 32
#define KV_HEAD 8
#define HEAD_DIM 128
#define GVS 64

// Scratch (static device globals; no allocations allowed)
__device__ float g_Q[S_LEN * D_MODEL];      // 32 MB
__device__ float g_K[S_LEN * GS_DIM];       // 8 MB
__device__ float g_V[S_LEN * GS_DIM];       // 8 MB
__device__ float g_AO[S_LEN * D_MODEL];     // 32 MB

// ---------------------------------------------------------------------------
// GEMM: C[M,N] = A[M,K] @ B[K,N] + bias[N]
// 128x128 CTA tile, K-step 8, 256 threads, 8x8 per-thread fragment.
// ---------------------------------------------------------------------------
__global__ __launch_bounds__(256) void gemm_bias_kernel(
    const float* __restrict__ A, const float* __restrict__ B,
    const float* __restrict__ bias, float* __restrict__ C,
    int M, int N, int K)
{
    __shared__ float As[8][128];
    __shared__ float Bs[8][128];

    const int tid = threadIdx.x;
    const int tx = tid & 15;
    const int ty = tid >> 4;
    const int m0 = blockIdx.y * 128;
    const int n0 = blockIdx.x * 128;

    float acc[8][8];
#pragma unroll
    for (int i = 0; i < 8; i++)
#pragma unroll
        for (int j = 0; j < 8; j++) acc[i][j] = 0.0f;

    const int ar = tid >> 1;
    const int ah = (tid & 1) * 4;
    const int br = tid >> 5;
    const int bc = (tid & 31) * 4;

    const float* Aptr = A + (size_t)(m0 + ar) * K + ah;
    const float* Bptr = B + (size_t)br * N + n0 + bc;

    for (int k0 = 0; k0 < K; k0 += 8) {
        float4 av = *(const float4*)(Aptr + k0);
        float4 bv = *(const float4*)(Bptr + (size_t)k0 * N);
        As[ah + 0][ar] = av.x;
        As[ah + 1][ar] = av.y;
        As[ah + 2][ar] = av.z;
        As[ah + 3][ar] = av.w;
        *(float4*)&Bs[br][bc] = bv;
        __syncthreads();

#pragma unroll
        for (int k = 0; k < 8; k++) {
            float a[8], b[8];
            *(float4*)(a)     = *(const float4*)&As[k][ty * 8];
            *(float4*)(a + 4) = *(const float4*)&As[k][ty * 8 + 4];
            *(float4*)(b)     = *(const float4*)&Bs[k][tx * 8];
            *(float4*)(b + 4) = *(const float4*)&Bs[k][tx * 8 + 4];
#pragma unroll
            for (int i = 0; i < 8; i++)
#pragma unroll
                for (int j = 0; j < 8; j++)
                    acc[i][j] += a[i] * b[j];
        }
        __syncthreads();
    }

#pragma unroll
    for (int i = 0; i < 8; i++) {
        const int m = m0 + ty * 8 + i;
        float* Crow = C + (size_t)m * N + n0 + tx * 8;
        const float* brow = bias + n0 + tx * 8;
#pragma unroll
        for (int j0 = 0; j0 < 8; j0 += 4) {
            float4 r;
            r.x = acc[i][j0 + 0] + brow[j0 + 0];
            r.y = acc[i][j0 + 1] + brow[j0 + 1];
            r.z = acc[i][j0 + 2] + brow[j0 + 2];
            r.w = acc[i][j0 + 3] + brow[j0 + 3];
            *(float4*)(Crow + j0) = r;
        }
    }
}

// ---------------------------------------------------------------------------
// RoPE (interleaved pairs), in place. T: [S, H, 128].
// NOTE: sincos(x, &sin, &cos) — SIN FIRST. (Round-1..6 bug was swapped args.)
// Double precision: exact range reduction for ang up to ~2047 rad.
// ---------------------------------------------------------------------------
__global__ void rope_kernel(float* __restrict__ T, int H)
{
    int idx = blockIdx.x * blockDim.x + threadIdx.x;
    int total = S_LEN * H * GVS;
    if (idx >= total) return;
    int i = idx % GVS;
    int h = (idx / GVS) % H;
    int s = idx / (GVS * H);
    double phi = exp(-((double)i / (double)GVS) * log(5000.0));
    double ang = (double)s * phi;
    double sn, c;
    sincos(ang, &sn, &c);       // sin first, cos second
    float cf = (float)c, sf = (float)sn;
    float* p = T + ((size_t)s * H + h) * HEAD_DIM + 2 * i;
    float tr = p[0], ti = p[1];
    p[0] = tr * cf - ti * sf;
    p[1] = tr * sf + ti * cf;
}

// ---------------------------------------------------------------------------
// Flash attention (fp32, causal, GQA module=4).
// One CTA per (q-tile of 64 rows, head). 256 threads.
// ---------------------------------------------------------------------------
#define AQ 64
#define AK 64
#define QPAD 132
#define SPAD 65

__global__ __launch_bounds__(256) void attn_kernel(
    const float* __restrict__ Q, const float* __restrict__ K,
    const float* __restrict__ V, float* __restrict__ O)
{
    extern __shared__ float sm[];
    float* Qs   = sm;
    float* KVs  = Qs + AQ * QPAD;
    float* Ss   = KVs + AK * QPAD;
    float* rowM = Ss + AQ * SPAD;
    float* rowL = rowM + AQ;
    float* rowA = rowL + AQ;

    const int tid = threadIdx.x;
    const int tx = tid & 15;
    const int ty = tid >> 4;
    const int qt = blockIdx.x;
    const int h  = blockIdx.y;
    const int q0 = qt * AQ;
    const int kvh = h >> 2;
    const float scale = 0.08838834764831845f;   // 1/sqrt(128)

    for (int t = tid; t < AQ * HEAD_DIM / 4; t += 256) {
        int m = t >> 5;
        int d4 = (t & 31) * 4;
        float4 v = *(const float4*)(Q + (size_t)(q0 + m) * D_MODEL + h * HEAD_DIM + d4);
        float* dst = Qs + m * QPAD + d4;
        dst[0] = v.x * scale; dst[1] = v.y * scale;
        dst[2] = v.z * scale; dst[3] = v.w * scale;
    }
    if (tid < AQ) { rowM[tid] = -1e30f; rowL[tid] = 0.0f; }

    float acc[4][8];
#pragma unroll
    for (int i = 0; i < 4; i++)
#pragma unroll
        for (int j = 0; j < 8; j++) acc[i][j] = 0.0f;

    for (int kt = 0; kt <= qt; kt++) {
        const int k0 = kt * AK;
        for (int t = tid; t < AK * HEAD_DIM / 4; t += 256) {
            int n = t >> 5;
            int d4 = (t & 31) * 4;
            *(float4*)(KVs + n * QPAD + d4) =
                *(const float4*)(K + (size_t)(k0 + n) * GS_DIM + kvh * HEAD_DIM + d4);
        }
        __syncthreads();

        float s4[4][4];
#pragma unroll
        for (int i = 0; i < 4; i++)
#pragma unroll
            for (int j = 0; j < 4; j++) s4[i][j] = 0.0f;

        for (int d = 0; d < HEAD_DIM; d += 4) {
            float4 a[4], b[4];
#pragma unroll
            for (int i = 0; i < 4; i++)
                a[i] = *(const float4*)&Qs[(ty * 4 + i) * QPAD + d];
#pragma unroll
            for (int j = 0; j < 4; j++)
                b[j] = *(const float4*)&KVs[(tx * 4 + j) * QPAD + d];
#pragma unroll
            for (int i = 0; i < 4; i++)
#pragma unroll
                for (int j = 0; j < 4; j++) {
                    s4[i][j] += a[i].x * b[j].x;
                    s4[i][j] += a[i].y * b[j].y;
                    s4[i][j] += a[i].z * b[j].z;
                    s4[i][j] += a[i].w * b[j].w;
                }
        }
        const bool diag = (kt == qt);
#pragma unroll
        for (int i = 0; i < 4; i++)
#pragma unroll
            for (int j = 0; j < 4; j++) {
                int m = ty * 4 + i, n = tx * 4 + j;
                float v = s4[i][j];
                if (diag && (k0 + n > q0 + m)) v = -1e30f;
                Ss[m * SPAD + n] = v;
            }
        __syncthreads();

        for (int t = tid; t < AK * HEAD_DIM / 4; t += 256) {
            int n = t >> 5;
            int d4 = (t & 31) * 4;
            *(float4*)(KVs + n * QPAD + d4) =
                *(const float4*)(V + (size_t)(k0 + n) * GS_DIM + kvh * HEAD_DIM + d4);
        }
        if (tid < AQ) {
            int m = tid;
            float mold = rowM[m];
            float mx = mold;
            for (int n = 0; n < AK; n++) mx = fmaxf(mx, Ss[m * SPAD + n]);
            float alpha = expf(mold - mx);
            float sum = 0.0f;
            for (int n = 0; n < AK; n++) {
                float p = expf(Ss[m * SPAD + n] - mx);
                Ss[m * SPAD + n] = p;
                sum += p;
            }
            rowL[m] = rowL[m] * alpha + sum;
            rowM[m] = mx;
            rowA[m] = alpha;
        }
        __syncthreads();

        float al[4];
#pragma unroll
        for (int i = 0; i < 4; i++) al[i] = rowA[ty * 4 + i];
#pragma unroll
        for (int i = 0; i < 4; i++)
#pragma unroll
            for (int j = 0; j < 8; j++) acc[i][j] *= al[i];

        for (int k = 0; k < AK; k++) {
            float p[4];
#pragma unroll
            for (int i = 0; i < 4; i++) p[i] = Ss[(ty * 4 + i) * SPAD + k];
            float v[8];
            *(float4*)(v)     = *(const float4*)&KVs[k * QPAD + tx * 8];
            *(float4*)(v + 4) = *(const float4*)&KVs[k * QPAD + tx * 8 + 4];
#pragma unroll
            for (int i = 0; i < 4; i++)
#pragma unroll
                for (int j = 0; j < 8; j++)
                    acc[i][j] += p[i] * v[j];
        }
        __syncthreads();
    }

#pragma unroll
    for (int i = 0; i < 4; i++) {
        int m = ty * 4 + i;
        float inv = 1.0f / rowL[m];
        float* orow = O + (size_t)(q0 + m) * D_MODEL + h * HEAD_DIM + tx * 8;
#pragma unroll
        for (int j0 = 0; j0 < 8; j0 += 4) {
            float4 r;
            r.x = acc[i][j0 + 0] * inv;
            r.y = acc[i][j0 + 1] * inv;
            r.z = acc[i][j0 + 2] * inv;
            r.w = acc[i][j0 + 3] * inv;
            *(float4*)(orow + j0) = r;
        }
    }
}

// ---------------------------------------------------------------------------
// Launch. Input order confirmed by R6 diagnostics (dict order):
//   0:x 1:y 2:Wq 3:bq 4:Wk 5:bk 6:Wv 7:bv 8:Wo 9:bo 10:n_head 11:kv_head
// ---------------------------------------------------------------------------
extern "C" void kernel_launch(void* const* d_in, const int* in_sizes, int n_in,
                              void* d_out, int out_size)
{
    (void)in_sizes; (void)n_in; (void)out_size;
    const float* x  = (const float*)d_in[0];
    const float* y  = (const float*)d_in[1];
    const float* Wq = (const float*)d_in[2];
    const float* bq = (const float*)d_in[3];
    const float* Wk = (const float*)d_in[4];
    const float* bk = (const float*)d_in[5];
    const float* Wv = (const float*)d_in[6];
    const float* bv = (const float*)d_in[7];
    const float* Wo = (const float*)d_in[8];
    const float* bo = (const float*)d_in[9];
    float* out = (float*)d_out;

    float *Qb, *Kb, *Vb, *AOb;
    cudaGetSymbolAddress((void**)&Qb, g_Q);
    cudaGetSymbolAddress((void**)&Kb, g_K);
    cudaGetSymbolAddress((void**)&Vb, g_V);
    cudaGetSymbolAddress((void**)&AOb, g_AO);

    const int smem_attn = (AQ * QPAD + AK * QPAD + AQ * SPAD + 3 * AQ) * (int)sizeof(float);
    cudaFuncSetAttribute(attn_kernel, cudaFuncAttributeMaxDynamicSharedMemorySize, smem_attn);

    // Q = x @ Wq + bq            [2048,4096]
    gemm_bias_kernel<<<dim3(D_MODEL / 128, S_LEN / 128), 256>>>(
        x, Wq, bq, Qb, S_LEN, D_MODEL, D_MODEL);
    // K = y @ Wk + bk            [2048,1024]
    gemm_bias_kernel<<<dim3(GS_DIM / 128, S_LEN / 128), 256>>>(
        y, Wk, bk, Kb, S_LEN, GS_DIM, D_MODEL);
    // V = y @ Wv + bv
    gemm_bias_kernel<<<dim3(GS_DIM / 128, S_LEN / 128), 256>>>(
        y, Wv, bv, Vb, S_LEN, GS_DIM, D_MODEL);

    // RoPE in place (fixed sincos argument order)
    {
        int totQ = S_LEN * N_HEAD * GVS;
        rope_kernel<<<(totQ + 255) / 256, 256>>>(Qb, N_HEAD);
        int totK = S_LEN * KV_HEAD * GVS;
        rope_kernel<<<(totK + 255) / 256, 256>>>(Kb, KV_HEAD);
    }

    // Attention
    attn_kernel<<<dim3(S_LEN / AQ, N_HEAD), 256, smem_attn>>>(Qb, Kb, Vb, AOb);

    // out = AO @ Wo + bo
    gemm_bias_kernel<<<dim3(D_MODEL / 128, S_LEN / 128), 256>>>(
        AOb, Wo, bo, out, S_LEN, D_MODEL, D_MODEL);
}

// round 8
// speedup vs baseline: 1.8246x; 1.8246x over previous
#include <cuda_runtime.h>
#include <cuda_bf16.h>
#include <math.h>
#include <stdint.h>

// ---------------------------------------------------------------------------
// Problem constants (B=1, S=2048, D=4096, n_head=32, kv_head=8, hd=128)
// ---------------------------------------------------------------------------
#define S_LEN 2048
#define D_MODEL 4096
#define GS_DIM 1024
#define N_HEAD 32
#define KV_HEAD 8
#define HEAD_DIM 128
#define GVS 64

// fp32 scratch
__device__ float g_Q[S_LEN * D_MODEL];
__device__ float g_K[S_LEN * GS_DIM];
__device__ float g_V[S_LEN * GS_DIM];
__device__ float g_AO[S_LEN * D_MODEL];
__device__ float2 g_tab[S_LEN * GVS];          // rope cos/sin table

// bf16 hi/lo splits
__device__ __nv_bfloat16 g_xh[S_LEN * D_MODEL],  g_xl[S_LEN * D_MODEL];
__device__ __nv_bfloat16 g_yh[S_LEN * D_MODEL],  g_yl[S_LEN * D_MODEL];
__device__ __nv_bfloat16 g_Wqh[D_MODEL * D_MODEL], g_Wql[D_MODEL * D_MODEL];
__device__ __nv_bfloat16 g_Wkh[D_MODEL * GS_DIM],  g_Wkl[D_MODEL * GS_DIM];
__device__ __nv_bfloat16 g_Wvh[D_MODEL * GS_DIM],  g_Wvl[D_MODEL * GS_DIM];
__device__ __nv_bfloat16 g_Woh[D_MODEL * D_MODEL], g_Wol[D_MODEL * D_MODEL];
__device__ __nv_bfloat16 g_AOh[S_LEN * D_MODEL],   g_AOl[S_LEN * D_MODEL];

// ---------------------------------------------------------------------------
// Split fp32 -> bf16 hi + bf16 residual  (v = hi + lo to ~2^-17 rel)
// ---------------------------------------------------------------------------
__global__ void split_kernel(const float* __restrict__ src,
                             __nv_bfloat16* __restrict__ hi,
                             __nv_bfloat16* __restrict__ lo, int n)
{
    int i = blockIdx.x * blockDim.x + threadIdx.x;
    if (i >= n) return;
    float v = src[i];
    __nv_bfloat16 h = __float2bfloat16(v);
    float r = v - __bfloat162float(h);
    hi[i] = h;
    lo[i] = __float2bfloat16(r);
}

// ---------------------------------------------------------------------------
// MMA helpers
// ---------------------------------------------------------------------------
__device__ __forceinline__ void ldmx4(uint32_t* r, const void* p)
{
    uint32_t a = (uint32_t)__cvta_generic_to_shared(p);
    asm volatile("ldmatrix.sync.aligned.m8n8.x4.shared.b16 {%0,%1,%2,%3}, [%4];"
                 : "=r"(r[0]), "=r"(r[1]), "=r"(r[2]), "=r"(r[3]) : "r"(a));
}
__device__ __forceinline__ void ldmx4t(uint32_t* r, const void* p)
{
    uint32_t a = (uint32_t)__cvta_generic_to_shared(p);
    asm volatile("ldmatrix.sync.aligned.m8n8.x4.trans.shared.b16 {%0,%1,%2,%3}, [%4];"
                 : "=r"(r[0]), "=r"(r[1]), "=r"(r[2]), "=r"(r[3]) : "r"(a));
}
__device__ __forceinline__ void mma16816(float* d, const uint32_t* a,
                                         uint32_t b0, uint32_t b1)
{
    asm volatile(
        "mma.sync.aligned.m16n8k16.row.col.f32.bf16.bf16.f32 "
        "{%0,%1,%2,%3}, {%4,%5,%6,%7}, {%8,%9}, {%0,%1,%2,%3};"
        : "+f"(d[0]), "+f"(d[1]), "+f"(d[2]), "+f"(d[3])
        : "r"(a[0]), "r"(a[1]), "r"(a[2]), "r"(a[3]), "r"(b0), "r"(b1));
}

// ---------------------------------------------------------------------------
// Split-bf16 3-pass GEMM: C[M,N] = (Ah+Al)@(Bh+Bl) + bias  (drop Al*Bl)
// CTA 128x128, k-step 32, 8 warps of 64x32. A row-major, B row-major [K][N].
// ---------------------------------------------------------------------------
#define BM 128
#define BN 128
#define BK 32
#define A_STRIDE 40
#define B_STRIDE 136

__global__ __launch_bounds__(256) void gemm_mma_kernel(
    const __nv_bfloat16* __restrict__ Ah, const __nv_bfloat16* __restrict__ Al,
    const __nv_bfloat16* __restrict__ Bh, const __nv_bfloat16* __restrict__ Bl,
    const float* __restrict__ bias, float* __restrict__ C,
    int M, int N, int K)
{
    __shared__ __nv_bfloat16 As[2][BM][A_STRIDE];   // [hi/lo][m][k]
    __shared__ __nv_bfloat16 Bs[2][BK][B_STRIDE];   // [hi/lo][k][n]

    const int tid  = threadIdx.x;
    const int lane = tid & 31;
    const int wid  = tid >> 5;
    const int wm   = (wid >> 2) * 64;   // 0 or 64
    const int wn   = (wid & 3) * 32;    // 0,32,64,96
    const int m0   = blockIdx.y * BM;
    const int n0   = blockIdx.x * BN;

    // staging indices
    const int arow = tid >> 1;          // 0..127
    const int acol = (tid & 1) * 16;    // 0 or 16
    const int brow = tid >> 3;          // 0..31
    const int bcol = (tid & 7) * 16;    // 0..112

    const uint4* gAh = (const uint4*)(Ah + (size_t)(m0 + arow) * K + acol);
    const uint4* gAl = (const uint4*)(Al + (size_t)(m0 + arow) * K + acol);

    float acc[4][4][4];
#pragma unroll
    for (int i = 0; i < 4; i++)
#pragma unroll
        for (int j = 0; j < 4; j++)
#pragma unroll
            for (int v = 0; v < 4; v++) acc[i][j][v] = 0.0f;

    for (int k0 = 0; k0 < K; k0 += BK) {
        // stage A (each thread: 16 bf16 hi + 16 lo = 2+2 uint4)
        {
            const uint4* pa = gAh + (k0 >> 3);   // k0/8 uint4 (8 bf16 per uint4)
            uint4 v0 = pa[0], v1 = pa[1];
            uint4* d = (uint4*)&As[0][arow][acol];
            d[0] = v0; d[1] = v1;
            const uint4* pb = gAl + (k0 >> 3);
            uint4 w0 = pb[0], w1 = pb[1];
            uint4* e = (uint4*)&As[1][arow][acol];
            e[0] = w0; e[1] = w1;
        }
        // stage B
        {
            const uint4* pa = (const uint4*)(Bh + (size_t)(k0 + brow) * N + n0 + bcol);
            uint4 v0 = pa[0], v1 = pa[1];
            uint4* d = (uint4*)&Bs[0][brow][bcol];
            d[0] = v0; d[1] = v1;
            const uint4* pb = (const uint4*)(Bl + (size_t)(k0 + brow) * N + n0 + bcol);
            uint4 w0 = pb[0], w1 = pb[1];
            uint4* e = (uint4*)&Bs[1][brow][bcol];
            e[0] = w0; e[1] = w1;
        }
        __syncthreads();

#pragma unroll
        for (int kk = 0; kk < BK; kk += 16) {
            uint32_t ah[4][4], al[4][4], bh[2][4], bl[2][4];
            const int lrow = lane & 15;
            const int lcol = (lane >> 4) * 8;
#pragma unroll
            for (int mt = 0; mt < 4; mt++) {
                ldmx4(ah[mt], &As[0][wm + mt * 16 + lrow][kk + lcol]);
                ldmx4(al[mt], &As[1][wm + mt * 16 + lrow][kk + lcol]);
            }
#pragma unroll
            for (int ntp = 0; ntp < 2; ntp++) {
                ldmx4t(bh[ntp], &Bs[0][kk + lrow][wn + ntp * 16 + lcol]);
                ldmx4t(bl[ntp], &Bs[1][kk + lrow][wn + ntp * 16 + lcol]);
            }
#pragma unroll
            for (int mt = 0; mt < 4; mt++)
#pragma unroll
                for (int nt = 0; nt < 4; nt++) {
                    const int ntp = nt >> 1, off = (nt & 1) * 2;
                    mma16816(acc[mt][nt], ah[mt], bh[ntp][off], bh[ntp][off + 1]);
                    mma16816(acc[mt][nt], ah[mt], bl[ntp][off], bl[ntp][off + 1]);
                    mma16816(acc[mt][nt], al[mt], bh[ntp][off], bh[ntp][off + 1]);
                }
        }
        __syncthreads();
    }

    // epilogue: bias + store (c-frag: rows lane>>2, +8; cols (lane&3)*2, +1)
    const int er = lane >> 2;
    const int ec = (lane & 3) * 2;
#pragma unroll
    for (int mt = 0; mt < 4; mt++)
#pragma unroll
        for (int nt = 0; nt < 4; nt++) {
            int r0 = m0 + wm + mt * 16 + er;
            int c0 = n0 + wn + nt * 8 + ec;
            float b0 = bias[c0], b1 = bias[c0 + 1];
            float2 v0 = make_float2(acc[mt][nt][0] + b0, acc[mt][nt][1] + b1);
            float2 v1 = make_float2(acc[mt][nt][2] + b0, acc[mt][nt][3] + b1);
            *(float2*)(C + (size_t)r0 * N + c0) = v0;
            *(float2*)(C + (size_t)(r0 + 8) * N + c0) = v1;
        }
}

// ---------------------------------------------------------------------------
// RoPE: build table (131K fp64 sincos) then apply (fp32, table reads)
// ---------------------------------------------------------------------------
__global__ void rope_table_kernel()
{
    int idx = blockIdx.x * blockDim.x + threadIdx.x;
    if (idx >= S_LEN * GVS) return;
    int s = idx / GVS, i = idx % GVS;
    double phi = exp(-((double)i / (double)GVS) * log(5000.0));
    double sn, c;
    sincos((double)s * phi, &sn, &c);     // sin first, cos second
    g_tab[idx] = make_float2((float)c, (float)sn);
}

__global__ void rope_apply_kernel(float* __restrict__ T, int H)
{
    int idx = blockIdx.x * blockDim.x + threadIdx.x;
    int total = S_LEN * H * GVS;
    if (idx >= total) return;
    int i = idx % GVS;
    int h = (idx / GVS) % H;
    int s = idx / (GVS * H);
    float2 cs = g_tab[s * GVS + i];
    float* p = T + ((size_t)s * H + h) * HEAD_DIM + 2 * i;
    float tr = p[0], ti = p[1];
    p[0] = tr * cs.x - ti * cs.y;
    p[1] = tr * cs.y + ti * cs.x;
}

// ---------------------------------------------------------------------------
// Flash attention (fp32, causal, GQA module=4) — unchanged from R7
// ---------------------------------------------------------------------------
#define AQ 64
#define AK 64
#define QPAD 132
#define SPAD 65

__global__ __launch_bounds__(256) void attn_kernel(
    const float* __restrict__ Q, const float* __restrict__ K,
    const float* __restrict__ V, float* __restrict__ O)
{
    extern __shared__ float sm[];
    float* Qs   = sm;
    float* KVs  = Qs + AQ * QPAD;
    float* Ss   = KVs + AK * QPAD;
    float* rowM = Ss + AQ * SPAD;
    float* rowL = rowM + AQ;
    float* rowA = rowL + AQ;

    const int tid = threadIdx.x;
    const int tx = tid & 15;
    const int ty = tid >> 4;
    const int qt = blockIdx.x;
    const int h  = blockIdx.y;
    const int q0 = qt * AQ;
    const int kvh = h >> 2;
    const float scale = 0.08838834764831845f;

    for (int t = tid; t < AQ * HEAD_DIM / 4; t += 256) {
        int m = t >> 5;
        int d4 = (t & 31) * 4;
        float4 v = *(const float4*)(Q + (size_t)(q0 + m) * D_MODEL + h * HEAD_DIM + d4);
        float* dst = Qs + m * QPAD + d4;
        dst[0] = v.x * scale; dst[1] = v.y * scale;
        dst[2] = v.z * scale; dst[3] = v.w * scale;
    }
    if (tid < AQ) { rowM[tid] = -1e30f; rowL[tid] = 0.0f; }

    float acc[4][8];
#pragma unroll
    for (int i = 0; i < 4; i++)
#pragma unroll
        for (int j = 0; j < 8; j++) acc[i][j] = 0.0f;

    for (int kt = 0; kt <= qt; kt++) {
        const int k0 = kt * AK;
        for (int t = tid; t < AK * HEAD_DIM / 4; t += 256) {
            int n = t >> 5;
            int d4 = (t & 31) * 4;
            *(float4*)(KVs + n * QPAD + d4) =
                *(const float4*)(K + (size_t)(k0 + n) * GS_DIM + kvh * HEAD_DIM + d4);
        }
        __syncthreads();

        float s4[4][4];
#pragma unroll
        for (int i = 0; i < 4; i++)
#pragma unroll
            for (int j = 0; j < 4; j++) s4[i][j] = 0.0f;

        for (int d = 0; d < HEAD_DIM; d += 4) {
            float4 a[4], b[4];
#pragma unroll
            for (int i = 0; i < 4; i++)
                a[i] = *(const float4*)&Qs[(ty * 4 + i) * QPAD + d];
#pragma unroll
            for (int j = 0; j < 4; j++)
                b[j] = *(const float4*)&KVs[(tx * 4 + j) * QPAD + d];
#pragma unroll
            for (int i = 0; i < 4; i++)
#pragma unroll
                for (int j = 0; j < 4; j++) {
                    s4[i][j] += a[i].x * b[j].x;
                    s4[i][j] += a[i].y * b[j].y;
                    s4[i][j] += a[i].z * b[j].z;
                    s4[i][j] += a[i].w * b[j].w;
                }
        }
        const bool diag = (kt == qt);
#pragma unroll
        for (int i = 0; i < 4; i++)
#pragma unroll
            for (int j = 0; j < 4; j++) {
                int m = ty * 4 + i, n = tx * 4 + j;
                float v = s4[i][j];
                if (diag && (k0 + n > q0 + m)) v = -1e30f;
                Ss[m * SPAD + n] = v;
            }
        __syncthreads();

        for (int t = tid; t < AK * HEAD_DIM / 4; t += 256) {
            int n = t >> 5;
            int d4 = (t & 31) * 4;
            *(float4*)(KVs + n * QPAD + d4) =
                *(const float4*)(V + (size_t)(k0 + n) * GS_DIM + kvh * HEAD_DIM + d4);
        }
        if (tid < AQ) {
            int m = tid;
            float mold = rowM[m];
            float mx = mold;
            for (int n = 0; n < AK; n++) mx = fmaxf(mx, Ss[m * SPAD + n]);
            float alpha = expf(mold - mx);
            float sum = 0.0f;
            for (int n = 0; n < AK; n++) {
                float p = expf(Ss[m * SPAD + n] - mx);
                Ss[m * SPAD + n] = p;
                sum += p;
            }
            rowL[m] = rowL[m] * alpha + sum;
            rowM[m] = mx;
            rowA[m] = alpha;
        }
        __syncthreads();

        float al[4];
#pragma unroll
        for (int i = 0; i < 4; i++) al[i] = rowA[ty * 4 + i];
#pragma unroll
        for (int i = 0; i < 4; i++)
#pragma unroll
            for (int j = 0; j < 8; j++) acc[i][j] *= al[i];

        for (int k = 0; k < AK; k++) {
            float p[4];
#pragma unroll
            for (int i = 0; i < 4; i++) p[i] = Ss[(ty * 4 + i) * SPAD + k];
            float v[8];
            *(float4*)(v)     = *(const float4*)&KVs[k * QPAD + tx * 8];
            *(float4*)(v + 4) = *(const float4*)&KVs[k * QPAD + tx * 8 + 4];
#pragma unroll
            for (int i = 0; i < 4; i++)
#pragma unroll
                for (int j = 0; j < 8; j++)
                    acc[i][j] += p[i] * v[j];
        }
        __syncthreads();
    }

#pragma unroll
    for (int i = 0; i < 4; i++) {
        int m = ty * 4 + i;
        float inv = 1.0f / rowL[m];
        float* orow = O + (size_t)(q0 + m) * D_MODEL + h * HEAD_DIM + tx * 8;
#pragma unroll
        for (int j0 = 0; j0 < 8; j0 += 4) {
            float4 r;
            r.x = acc[i][j0 + 0] * inv;
            r.y = acc[i][j0 + 1] * inv;
            r.z = acc[i][j0 + 2] * inv;
            r.w = acc[i][j0 + 3] * inv;
            *(float4*)(orow + j0) = r;
        }
    }
}

// ---------------------------------------------------------------------------
// Launch. Input order (confirmed by R6 diagnostics, dict order):
//   0:x 1:y 2:Wq 3:bq 4:Wk 5:bk 6:Wv 7:bv 8:Wo 9:bo 10:n_head 11:kv_head
// ---------------------------------------------------------------------------
static inline void split(const float* s, __nv_bfloat16* h, __nv_bfloat16* l, int n)
{
    split_kernel<<<(n + 255) / 256, 256>>>(s, h, l, n);
}

extern "C" void kernel_launch(void* const* d_in, const int* in_sizes, int n_in,
                              void* d_out, int out_size)
{
    (void)in_sizes; (void)n_in; (void)out_size;
    const float* x  = (const float*)d_in[0];
    const float* y  = (const float*)d_in[1];
    const float* Wq = (const float*)d_in[2];
    const float* bq = (const float*)d_in[3];
    const float* Wk = (const float*)d_in[4];
    const float* bk = (const float*)d_in[5];
    const float* Wv = (const float*)d_in[6];
    const float* bv = (const float*)d_in[7];
    const float* Wo = (const float*)d_in[8];
    const float* bo = (const float*)d_in[9];
    float* out = (float*)d_out;

    float *Qb, *Kb, *Vb, *AOb;
    cudaGetSymbolAddress((void**)&Qb, g_Q);
    cudaGetSymbolAddress((void**)&Kb, g_K);
    cudaGetSymbolAddress((void**)&Vb, g_V);
    cudaGetSymbolAddress((void**)&AOb, g_AO);

    __nv_bfloat16 *xh, *xl, *yh, *yl, *Wqh, *Wql, *Wkh, *Wkl, *Wvh, *Wvl,
                  *Woh, *Wol, *AOh, *AOl;
    cudaGetSymbolAddress((void**)&xh, g_xh);   cudaGetSymbolAddress((void**)&xl, g_xl);
    cudaGetSymbolAddress((void**)&yh, g_yh);   cudaGetSymbolAddress((void**)&yl, g_yl);
    cudaGetSymbolAddress((void**)&Wqh, g_Wqh); cudaGetSymbolAddress((void**)&Wql, g_Wql);
    cudaGetSymbolAddress((void**)&Wkh, g_Wkh); cudaGetSymbolAddress((void**)&Wkl, g_Wkl);
    cudaGetSymbolAddress((void**)&Wvh, g_Wvh); cudaGetSymbolAddress((void**)&Wvl, g_Wvl);
    cudaGetSymbolAddress((void**)&Woh, g_Woh); cudaGetSymbolAddress((void**)&Wol, g_Wol);
    cudaGetSymbolAddress((void**)&AOh, g_AOh); cudaGetSymbolAddress((void**)&AOl, g_AOl);

    const int smem_attn = (AQ * QPAD + AK * QPAD + AQ * SPAD + 3 * AQ) * (int)sizeof(float);
    cudaFuncSetAttribute(attn_kernel, cudaFuncAttributeMaxDynamicSharedMemorySize, smem_attn);

    // 0..2: Q projection
    split(x, xh, xl, S_LEN * D_MODEL);
    split(Wq, Wqh, Wql, D_MODEL * D_MODEL);
    gemm_mma_kernel<<<dim3(D_MODEL / BN, S_LEN / BM), 256>>>(
        xh, xl, Wqh, Wql, bq, Qb, S_LEN, D_MODEL, D_MODEL);
    // 3..5: K projection (launch #5 = gemm K -> profiled by ncu)
    split(y, yh, yl, S_LEN * D_MODEL);
    split(Wk, Wkh, Wkl, D_MODEL * GS_DIM);
    gemm_mma_kernel<<<dim3(GS_DIM / BN, S_LEN / BM), 256>>>(
        yh, yl, Wkh, Wkl, bk, Kb, S_LEN, GS_DIM, D_MODEL);
    // 6..7: V projection
    split(Wv, Wvh, Wvl, D_MODEL * GS_DIM);
    gemm_mma_kernel<<<dim3(GS_DIM / BN, S_LEN / BM), 256>>>(
        yh, yl, Wvh, Wvl, bv, Vb, S_LEN, GS_DIM, D_MODEL);

    // 8..10: RoPE
    rope_table_kernel<<<(S_LEN * GVS + 255) / 256, 256>>>();
    rope_apply_kernel<<<(S_LEN * N_HEAD * GVS + 255) / 256, 256>>>(Qb, N_HEAD);
    rope_apply_kernel<<<(S_LEN * KV_HEAD * GVS + 255) / 256, 256>>>(Kb, KV_HEAD);

    // 11: attention
    attn_kernel<<<dim3(S_LEN / AQ, N_HEAD), 256, smem_attn>>>(Qb, Kb, Vb, AOb);

    // 12..14: output projection
    split(Wo, Woh, Wol, D_MODEL * D_MODEL);
    split(AOb, AOh, AOl, S_LEN * D_MODEL);
    gemm_mma_kernel<<<dim3(D_MODEL / BN, S_LEN / BM), 256>>>(
        AOh, AOl, Woh, Wol, bo, out, S_LEN, D_MODEL, D_MODEL);
}

// round 9
// speedup vs baseline: 1.9909x; 1.0912x over previous
#include <cuda_runtime.h>
#include <cuda_bf16.h>
#include <math.h>
#include <stdint.h>

// ---------------------------------------------------------------------------
// Problem constants (B=1, S=2048, D=4096, n_head=32, kv_head=8, hd=128)
// ---------------------------------------------------------------------------
#define S_LEN 2048
#define D_MODEL 4096
#define GS_DIM 1024
#define N_HEAD 32
#define KV_HEAD 8
#define HEAD_DIM 128
#define GVS 64

// fp32 scratch
__device__ float g_Q[S_LEN * D_MODEL];
__device__ float g_K[S_LEN * GS_DIM];
__device__ float g_V[S_LEN * GS_DIM];
__device__ float g_AO[S_LEN * D_MODEL];
__device__ float2 g_tab[S_LEN * GVS];

// bf16 hi/lo splits
__device__ __nv_bfloat16 g_xh[S_LEN * D_MODEL],  g_xl[S_LEN * D_MODEL];
__device__ __nv_bfloat16 g_yh[S_LEN * D_MODEL],  g_yl[S_LEN * D_MODEL];
__device__ __nv_bfloat16 g_Wqh[D_MODEL * D_MODEL], g_Wql[D_MODEL * D_MODEL];
__device__ __nv_bfloat16 g_Wkh[D_MODEL * GS_DIM],  g_Wkl[D_MODEL * GS_DIM];
__device__ __nv_bfloat16 g_Wvh[D_MODEL * GS_DIM],  g_Wvl[D_MODEL * GS_DIM];
__device__ __nv_bfloat16 g_Woh[D_MODEL * D_MODEL], g_Wol[D_MODEL * D_MODEL];
__device__ __nv_bfloat16 g_AOh[S_LEN * D_MODEL],   g_AOl[S_LEN * D_MODEL];
__device__ __nv_bfloat16 g_Qh[S_LEN * D_MODEL],    g_Ql[S_LEN * D_MODEL];
__device__ __nv_bfloat16 g_Kh[S_LEN * GS_DIM],     g_Kl[S_LEN * GS_DIM];
__device__ __nv_bfloat16 g_Vh[S_LEN * GS_DIM],     g_Vl[S_LEN * GS_DIM];

// ---------------------------------------------------------------------------
// Split fp32*scale -> bf16 hi + bf16 residual
// ---------------------------------------------------------------------------
__global__ void split_kernel(const float* __restrict__ src,
                             __nv_bfloat16* __restrict__ hi,
                             __nv_bfloat16* __restrict__ lo, int n, float scale)
{
    int i = blockIdx.x * blockDim.x + threadIdx.x;
    if (i >= n) return;
    float v = src[i] * scale;
    __nv_bfloat16 h = __float2bfloat16(v);
    hi[i] = h;
    lo[i] = __float2bfloat16(v - __bfloat162float(h));
}

// ---------------------------------------------------------------------------
// MMA helpers
// ---------------------------------------------------------------------------
__device__ __forceinline__ void ldmx4(uint32_t* r, const void* p)
{
    uint32_t a = (uint32_t)__cvta_generic_to_shared(p);
    asm volatile("ldmatrix.sync.aligned.m8n8.x4.shared.b16 {%0,%1,%2,%3}, [%4];"
                 : "=r"(r[0]), "=r"(r[1]), "=r"(r[2]), "=r"(r[3]) : "r"(a));
}
__device__ __forceinline__ void ldmx4t(uint32_t* r, const void* p)
{
    uint32_t a = (uint32_t)__cvta_generic_to_shared(p);
    asm volatile("ldmatrix.sync.aligned.m8n8.x4.trans.shared.b16 {%0,%1,%2,%3}, [%4];"
                 : "=r"(r[0]), "=r"(r[1]), "=r"(r[2]), "=r"(r[3]) : "r"(a));
}
__device__ __forceinline__ void mma16816(float* d, const uint32_t* a,
                                         uint32_t b0, uint32_t b1)
{
    asm volatile(
        "mma.sync.aligned.m16n8k16.row.col.f32.bf16.bf16.f32 "
        "{%0,%1,%2,%3}, {%4,%5,%6,%7}, {%8,%9}, {%0,%1,%2,%3};"
        : "+f"(d[0]), "+f"(d[1]), "+f"(d[2]), "+f"(d[3])
        : "r"(a[0]), "r"(a[1]), "r"(a[2]), "r"(a[3]), "r"(b0), "r"(b1));
}

// ---------------------------------------------------------------------------
// Split-bf16 3-pass GEMM (unchanged from R8, known good)
// ---------------------------------------------------------------------------
#define BM 128
#define BN 128
#define BK 32
#define A_STRIDE 40
#define B_STRIDE 136

__global__ __launch_bounds__(256) void gemm_mma_kernel(
    const __nv_bfloat16* __restrict__ Ah, const __nv_bfloat16* __restrict__ Al,
    const __nv_bfloat16* __restrict__ Bh, const __nv_bfloat16* __restrict__ Bl,
    const float* __restrict__ bias, float* __restrict__ C,
    int M, int N, int K)
{
    __shared__ __nv_bfloat16 As[2][BM][A_STRIDE];
    __shared__ __nv_bfloat16 Bs[2][BK][B_STRIDE];

    const int tid  = threadIdx.x;
    const int lane = tid & 31;
    const int wid  = tid >> 5;
    const int wm   = (wid >> 2) * 64;
    const int wn   = (wid & 3) * 32;
    const int m0   = blockIdx.y * BM;
    const int n0   = blockIdx.x * BN;

    const int arow = tid >> 1;
    const int acol = (tid & 1) * 16;
    const int brow = tid >> 3;
    const int bcol = (tid & 7) * 16;

    const uint4* gAh = (const uint4*)(Ah + (size_t)(m0 + arow) * K + acol);
    const uint4* gAl = (const uint4*)(Al + (size_t)(m0 + arow) * K + acol);

    float acc[4][4][4];
#pragma unroll
    for (int i = 0; i < 4; i++)
#pragma unroll
        for (int j = 0; j < 4; j++)
#pragma unroll
            for (int v = 0; v < 4; v++) acc[i][j][v] = 0.0f;

    for (int k0 = 0; k0 < K; k0 += BK) {
        {
            const uint4* pa = gAh + (k0 >> 3);
            uint4 v0 = pa[0], v1 = pa[1];
            uint4* d = (uint4*)&As[0][arow][acol];
            d[0] = v0; d[1] = v1;
            const uint4* pb = gAl + (k0 >> 3);
            uint4 w0 = pb[0], w1 = pb[1];
            uint4* e = (uint4*)&As[1][arow][acol];
            e[0] = w0; e[1] = w1;
        }
        {
            const uint4* pa = (const uint4*)(Bh + (size_t)(k0 + brow) * N + n0 + bcol);
            uint4 v0 = pa[0], v1 = pa[1];
            uint4* d = (uint4*)&Bs[0][brow][bcol];
            d[0] = v0; d[1] = v1;
            const uint4* pb = (const uint4*)(Bl + (size_t)(k0 + brow) * N + n0 + bcol);
            uint4 w0 = pb[0], w1 = pb[1];
            uint4* e = (uint4*)&Bs[1][brow][bcol];
            e[0] = w0; e[1] = w1;
        }
        __syncthreads();

#pragma unroll
        for (int kk = 0; kk < BK; kk += 16) {
            uint32_t ah[4][4], al[4][4], bh[2][4], bl[2][4];
            const int lrow = lane & 15;
            const int lcol = (lane >> 4) * 8;
#pragma unroll
            for (int mt = 0; mt < 4; mt++) {
                ldmx4(ah[mt], &As[0][wm + mt * 16 + lrow][kk + lcol]);
                ldmx4(al[mt], &As[1][wm + mt * 16 + lrow][kk + lcol]);
            }
#pragma unroll
            for (int ntp = 0; ntp < 2; ntp++) {
                ldmx4t(bh[ntp], &Bs[0][kk + lrow][wn + ntp * 16 + lcol]);
                ldmx4t(bl[ntp], &Bs[1][kk + lrow][wn + ntp * 16 + lcol]);
            }
#pragma unroll
            for (int mt = 0; mt < 4; mt++)
#pragma unroll
                for (int nt = 0; nt < 4; nt++) {
                    const int ntp = nt >> 1, off = (nt & 1) * 2;
                    mma16816(acc[mt][nt], ah[mt], bh[ntp][off], bh[ntp][off + 1]);
                    mma16816(acc[mt][nt], ah[mt], bl[ntp][off], bl[ntp][off + 1]);
                    mma16816(acc[mt][nt], al[mt], bh[ntp][off], bh[ntp][off + 1]);
                }
        }
        __syncthreads();
    }

    const int er = lane >> 2;
    const int ec = (lane & 3) * 2;
#pragma unroll
    for (int mt = 0; mt < 4; mt++)
#pragma unroll
        for (int nt = 0; nt < 4; nt++) {
            int r0 = m0 + wm + mt * 16 + er;
            int c0 = n0 + wn + nt * 8 + ec;
            float b0 = bias[c0], b1 = bias[c0 + 1];
            float2 v0 = make_float2(acc[mt][nt][0] + b0, acc[mt][nt][1] + b1);
            float2 v1 = make_float2(acc[mt][nt][2] + b0, acc[mt][nt][3] + b1);
            *(float2*)(C + (size_t)r0 * N + c0) = v0;
            *(float2*)(C + (size_t)(r0 + 8) * N + c0) = v1;
        }
}

// ---------------------------------------------------------------------------
// RoPE table + apply
// ---------------------------------------------------------------------------
__global__ void rope_table_kernel()
{
    int idx = blockIdx.x * blockDim.x + threadIdx.x;
    if (idx >= S_LEN * GVS) return;
    int s = idx / GVS, i = idx % GVS;
    double phi = exp(-((double)i / (double)GVS) * log(5000.0));
    double sn, c;
    sincos((double)s * phi, &sn, &c);   // sin first, cos second
    g_tab[idx] = make_float2((float)c, (float)sn);
}

__global__ void rope_apply_kernel(float* __restrict__ T, int H)
{
    int idx = blockIdx.x * blockDim.x + threadIdx.x;
    int total = S_LEN * H * GVS;
    if (idx >= total) return;
    int i = idx % GVS;
    int h = (idx / GVS) % H;
    int s = idx / (GVS * H);
    float2 cs = g_tab[s * GVS + i];
    float* p = T + ((size_t)s * H + h) * HEAD_DIM + 2 * i;
    float tr = p[0], ti = p[1];
    p[0] = tr * cs.x - ti * cs.y;
    p[1] = tr * cs.y + ti * cs.x;
}

// ---------------------------------------------------------------------------
// MMA flash attention. CTA = (q-tile 128 rows, head). 256 thr = 8 warps x 16 rows.
// KV tiles of 64. Split-bf16 3-pass for both QK^T and PV.
// smem (bf16): Qh/Ql[128][136] | Kh/Kl[64][136] | Vh/Vl[64][136] | Ph/Pl[128][72]
// ---------------------------------------------------------------------------
#define QT 128
#define KT 64
#define DSTR 136
#define PSTR 72

__global__ __launch_bounds__(256) void attn_mma_kernel(
    const __nv_bfloat16* __restrict__ Qh, const __nv_bfloat16* __restrict__ Ql,
    const __nv_bfloat16* __restrict__ Kh, const __nv_bfloat16* __restrict__ Kl,
    const __nv_bfloat16* __restrict__ Vh, const __nv_bfloat16* __restrict__ Vl,
    float* __restrict__ O)
{
    extern __shared__ __nv_bfloat16 sb[];
    __nv_bfloat16* sQh = sb;
    __nv_bfloat16* sQl = sQh + QT * DSTR;
    __nv_bfloat16* sKh = sQl + QT * DSTR;
    __nv_bfloat16* sKl = sKh + KT * DSTR;
    __nv_bfloat16* sVh = sKl + KT * DSTR;
    __nv_bfloat16* sVl = sVh + KT * DSTR;
    __nv_bfloat16* sPh = sVl + KT * DSTR;
    __nv_bfloat16* sPl = sPh + QT * PSTR;

    const int tid  = threadIdx.x;
    const int lane = tid & 31;
    const int wid  = tid >> 5;
    const int wrow = wid * 16;
    const int qt   = blockIdx.x;
    const int h    = blockIdx.y;
    const int q0   = qt * QT;
    const int kvh  = h >> 2;

    // Stage Q tile (128 x 128), hi+lo
    for (int t = tid; t < QT * 16; t += 256) {
        int r = t >> 4, c8 = (t & 15) * 8;
        const uint4* ph = (const uint4*)(Qh + (size_t)(q0 + r) * D_MODEL + h * HEAD_DIM + c8);
        const uint4* pl = (const uint4*)(Ql + (size_t)(q0 + r) * D_MODEL + h * HEAD_DIM + c8);
        *(uint4*)(sQh + r * DSTR + c8) = *ph;
        *(uint4*)(sQl + r * DSTR + c8) = *pl;
    }

    float oacc[16][4];
#pragma unroll
    for (int nt = 0; nt < 16; nt++)
#pragma unroll
        for (int v = 0; v < 4; v++) oacc[nt][v] = 0.0f;
    float m_lo = -1e30f, m_hi = -1e30f, l_lo = 0.0f, l_hi = 0.0f;

    const int lrow = lane & 15;
    const int lcol = (lane >> 4) * 8;
    const int er   = lane >> 2;          // fragment row 0..7
    const int ec   = (lane & 3) * 2;     // fragment col base

    const int ktmax = 2 * qt + 1;
    for (int kt = 0; kt <= ktmax; kt++) {
        const int k0 = kt * KT;
        __syncthreads();
        // stage K,V tile (64 x 128) hi+lo
        for (int t = tid; t < KT * 16; t += 256) {
            int r = t >> 4, c8 = (t & 15) * 8;
            size_t g = (size_t)(k0 + r) * GS_DIM + kvh * HEAD_DIM + c8;
            *(uint4*)(sKh + r * DSTR + c8) = *(const uint4*)(Kh + g);
            *(uint4*)(sKl + r * DSTR + c8) = *(const uint4*)(Kl + g);
            *(uint4*)(sVh + r * DSTR + c8) = *(const uint4*)(Vh + g);
            *(uint4*)(sVl + r * DSTR + c8) = *(const uint4*)(Vl + g);
        }
        __syncthreads();

        if (k0 > q0 + wrow + 15) continue;   // warp-block fully masked

        // ---- scores: 128-d contraction, 8 k-steps; 3 passes fused ----
        float sacc[8][4];
#pragma unroll
        for (int nt = 0; nt < 8; nt++)
#pragma unroll
            for (int v = 0; v < 4; v++) sacc[nt][v] = 0.0f;

#pragma unroll
        for (int kk = 0; kk < 8; kk++) {
            uint32_t ah[4], al[4];
            ldmx4(ah, sQh + (wrow + lrow) * DSTR + kk * 16 + lcol);
            ldmx4(al, sQl + (wrow + lrow) * DSTR + kk * 16 + lcol);
#pragma unroll
            for (int np = 0; np < 4; np++) {
                uint32_t bh[4], bl[4];
                // non-trans ldmatrix of K[key][d]: r0/r2 = ntile 2np (b0,b1), r1/r3 = ntile 2np+1
                ldmx4(bh, sKh + (np * 16 + lrow) * DSTR + kk * 16 + lcol);
                ldmx4(bl, sKl + (np * 16 + lrow) * DSTR + kk * 16 + lcol);
                mma16816(sacc[2 * np],     ah, bh[0], bh[2]);
                mma16816(sacc[2 * np],     ah, bl[0], bl[2]);
                mma16816(sacc[2 * np],     al, bh[0], bh[2]);
                mma16816(sacc[2 * np + 1], ah, bh[1], bh[3]);
                mma16816(sacc[2 * np + 1], ah, bl[1], bl[3]);
                mma16816(sacc[2 * np + 1], al, bh[1], bh[3]);
            }
        }

        // ---- causal mask (only possible on last two tiles) ----
        if (kt >= 2 * qt) {
            int gq_lo = q0 + wrow + er;
            int gq_hi = gq_lo + 8;
#pragma unroll
            for (int nt = 0; nt < 8; nt++) {
                int c0 = k0 + nt * 8 + ec;
                if (c0 > gq_lo)     sacc[nt][0] = -1e30f;
                if (c0 + 1 > gq_lo) sacc[nt][1] = -1e30f;
                if (c0 > gq_hi)     sacc[nt][2] = -1e30f;
                if (c0 + 1 > gq_hi) sacc[nt][3] = -1e30f;
            }
        }

        // ---- online softmax ----
        float mx_lo = -1e30f, mx_hi = -1e30f;
#pragma unroll
        for (int nt = 0; nt < 8; nt++) {
            mx_lo = fmaxf(mx_lo, fmaxf(sacc[nt][0], sacc[nt][1]));
            mx_hi = fmaxf(mx_hi, fmaxf(sacc[nt][2], sacc[nt][3]));
        }
        mx_lo = fmaxf(mx_lo, __shfl_xor_sync(0xffffffffu, mx_lo, 1));
        mx_lo = fmaxf(mx_lo, __shfl_xor_sync(0xffffffffu, mx_lo, 2));
        mx_hi = fmaxf(mx_hi, __shfl_xor_sync(0xffffffffu, mx_hi, 1));
        mx_hi = fmaxf(mx_hi, __shfl_xor_sync(0xffffffffu, mx_hi, 2));

        float mn_lo = fmaxf(m_lo, mx_lo);
        float mn_hi = fmaxf(m_hi, mx_hi);
        float al_lo = __expf(m_lo - mn_lo);
        float al_hi = __expf(m_hi - mn_hi);

        float sum_lo = 0.0f, sum_hi = 0.0f;
#pragma unroll
        for (int nt = 0; nt < 8; nt++) {
            float p0 = __expf(sacc[nt][0] - mn_lo);
            float p1 = __expf(sacc[nt][1] - mn_lo);
            float p2 = __expf(sacc[nt][2] - mn_hi);
            float p3 = __expf(sacc[nt][3] - mn_hi);
            sum_lo += p0 + p1;
            sum_hi += p2 + p3;
            // write P split to smem (hi + residual)
            int c = nt * 8 + ec;
            __nv_bfloat16 h0 = __float2bfloat16(p0);
            __nv_bfloat16 h1 = __float2bfloat16(p1);
            __nv_bfloat16 h2 = __float2bfloat16(p2);
            __nv_bfloat16 h3 = __float2bfloat16(p3);
            sPh[(wrow + er) * PSTR + c]     = h0;
            sPh[(wrow + er) * PSTR + c + 1] = h1;
            sPh[(wrow + er + 8) * PSTR + c]     = h2;
            sPh[(wrow + er + 8) * PSTR + c + 1] = h3;
            sPl[(wrow + er) * PSTR + c]     = __float2bfloat16(p0 - __bfloat162float(h0));
            sPl[(wrow + er) * PSTR + c + 1] = __float2bfloat16(p1 - __bfloat162float(h1));
            sPl[(wrow + er + 8) * PSTR + c]     = __float2bfloat16(p2 - __bfloat162float(h2));
            sPl[(wrow + er + 8) * PSTR + c + 1] = __float2bfloat16(p3 - __bfloat162float(h3));
        }
        sum_lo += __shfl_xor_sync(0xffffffffu, sum_lo, 1);
        sum_lo += __shfl_xor_sync(0xffffffffu, sum_lo, 2);
        sum_hi += __shfl_xor_sync(0xffffffffu, sum_hi, 1);
        sum_hi += __shfl_xor_sync(0xffffffffu, sum_hi, 2);

        l_lo = l_lo * al_lo + sum_lo;
        l_hi = l_hi * al_hi + sum_hi;
        m_lo = mn_lo; m_hi = mn_hi;

        // rescale O
#pragma unroll
        for (int nt = 0; nt < 16; nt++) {
            oacc[nt][0] *= al_lo; oacc[nt][1] *= al_lo;
            oacc[nt][2] *= al_hi; oacc[nt][3] *= al_hi;
        }
        __syncwarp();

        // ---- PV: k = 64 keys (4 k-steps), n = 128 dims (8 n-pairs) ----
#pragma unroll
        for (int kk = 0; kk < 4; kk++) {
            uint32_t ah[4], al2[4];
            ldmx4(ah,  sPh + (wrow + lrow) * PSTR + kk * 16 + lcol);
            ldmx4(al2, sPl + (wrow + lrow) * PSTR + kk * 16 + lcol);
#pragma unroll
            for (int np = 0; np < 8; np++) {
                uint32_t bh[4], bl[4];
                ldmx4t(bh, sVh + (kk * 16 + lrow) * DSTR + np * 16 + lcol);
                ldmx4t(bl, sVl + (kk * 16 + lrow) * DSTR + np * 16 + lcol);
                mma16816(oacc[2 * np],     ah,  bh[0], bh[1]);
                mma16816(oacc[2 * np],     al2, bh[0], bh[1]);
                mma16816(oacc[2 * np],     ah,  bl[0], bl[1]);
                mma16816(oacc[2 * np + 1], ah,  bh[2], bh[3]);
                mma16816(oacc[2 * np + 1], al2, bh[2], bh[3]);
                mma16816(oacc[2 * np + 1], ah,  bl[2], bl[3]);
            }
        }
    }

    // ---- epilogue ----
    float inv_lo = 1.0f / l_lo;
    float inv_hi = 1.0f / l_hi;
    int gq_lo = q0 + wrow + er;
#pragma unroll
    for (int nt = 0; nt < 16; nt++) {
        int c = h * HEAD_DIM + nt * 8 + ec;
        *(float2*)(O + (size_t)gq_lo * D_MODEL + c) =
            make_float2(oacc[nt][0] * inv_lo, oacc[nt][1] * inv_lo);
        *(float2*)(O + (size_t)(gq_lo + 8) * D_MODEL + c) =
            make_float2(oacc[nt][2] * inv_hi, oacc[nt][3] * inv_hi);
    }
}

// ---------------------------------------------------------------------------
// Launch. Input order (R6-confirmed dict order):
//   0:x 1:y 2:Wq 3:bq 4:Wk 5:bk 6:Wv 7:bv 8:Wo 9:bo
// ---------------------------------------------------------------------------
static inline void split(const float* s, __nv_bfloat16* h, __nv_bfloat16* l,
                         int n, float scale = 1.0f)
{
    split_kernel<<<(n + 255) / 256, 256>>>(s, h, l, n, scale);
}

extern "C" void kernel_launch(void* const* d_in, const int* in_sizes, int n_in,
                              void* d_out, int out_size)
{
    (void)in_sizes; (void)n_in; (void)out_size;
    const float* x  = (const float*)d_in[0];
    const float* y  = (const float*)d_in[1];
    const float* Wq = (const float*)d_in[2];
    const float* bq = (const float*)d_in[3];
    const float* Wk = (const float*)d_in[4];
    const float* bk = (const float*)d_in[5];
    const float* Wv = (const float*)d_in[6];
    const float* bv = (const float*)d_in[7];
    const float* Wo = (const float*)d_in[8];
    const float* bo = (const float*)d_in[9];
    float* out = (float*)d_out;

    float *Qb, *Kb, *Vb, *AOb;
    cudaGetSymbolAddress((void**)&Qb, g_Q);
    cudaGetSymbolAddress((void**)&Kb, g_K);
    cudaGetSymbolAddress((void**)&Vb, g_V);
    cudaGetSymbolAddress((void**)&AOb, g_AO);

    __nv_bfloat16 *xh, *xl, *yh, *yl, *Wqh, *Wql, *Wkh, *Wkl, *Wvh, *Wvl,
                  *Woh, *Wol, *AOh, *AOl, *Qsh, *Qsl, *Ksh, *Ksl, *Vsh, *Vsl;
    cudaGetSymbolAddress((void**)&xh, g_xh);   cudaGetSymbolAddress((void**)&xl, g_xl);
    cudaGetSymbolAddress((void**)&yh, g_yh);   cudaGetSymbolAddress((void**)&yl, g_yl);
    cudaGetSymbolAddress((void**)&Wqh, g_Wqh); cudaGetSymbolAddress((void**)&Wql, g_Wql);
    cudaGetSymbolAddress((void**)&Wkh, g_Wkh); cudaGetSymbolAddress((void**)&Wkl, g_Wkl);
    cudaGetSymbolAddress((void**)&Wvh, g_Wvh); cudaGetSymbolAddress((void**)&Wvl, g_Wvl);
    cudaGetSymbolAddress((void**)&Woh, g_Woh); cudaGetSymbolAddress((void**)&Wol, g_Wol);
    cudaGetSymbolAddress((void**)&AOh, g_AOh); cudaGetSymbolAddress((void**)&AOl, g_AOl);
    cudaGetSymbolAddress((void**)&Qsh, g_Qh);  cudaGetSymbolAddress((void**)&Qsl, g_Ql);
    cudaGetSymbolAddress((void**)&Ksh, g_Kh);  cudaGetSymbolAddress((void**)&Ksl, g_Kl);
    cudaGetSymbolAddress((void**)&Vsh, g_Vh);  cudaGetSymbolAddress((void**)&Vsl, g_Vl);

    const int smem_attn = (2 * QT * DSTR + 4 * KT * DSTR + 2 * QT * PSTR) * 2;
    cudaFuncSetAttribute(attn_mma_kernel, cudaFuncAttributeMaxDynamicSharedMemorySize, smem_attn);

    // Projections
    split(x, xh, xl, S_LEN * D_MODEL);
    split(Wq, Wqh, Wql, D_MODEL * D_MODEL);
    gemm_mma_kernel<<<dim3(D_MODEL / BN, S_LEN / BM), 256>>>(
        xh, xl, Wqh, Wql, bq, Qb, S_LEN, D_MODEL, D_MODEL);
    split(y, yh, yl, S_LEN * D_MODEL);
    split(Wk, Wkh, Wkl, D_MODEL * GS_DIM);
    gemm_mma_kernel<<<dim3(GS_DIM / BN, S_LEN / BM), 256>>>(
        yh, yl, Wkh, Wkl, bk, Kb, S_LEN, GS_DIM, D_MODEL);
    split(Wv, Wvh, Wvl, D_MODEL * GS_DIM);
    gemm_mma_kernel<<<dim3(GS_DIM / BN, S_LEN / BM), 256>>>(
        yh, yl, Wvh, Wvl, bv, Vb, S_LEN, GS_DIM, D_MODEL);

    // RoPE
    rope_table_kernel<<<(S_LEN * GVS + 255) / 256, 256>>>();
    rope_apply_kernel<<<(S_LEN * N_HEAD * GVS + 255) / 256, 256>>>(Qb, N_HEAD);
    rope_apply_kernel<<<(S_LEN * KV_HEAD * GVS + 255) / 256, 256>>>(Kb, KV_HEAD);

    // Attention pre-splits (scale folded into Q)
    split(Qb, Qsh, Qsl, S_LEN * D_MODEL, 0.08838834764831845f);
    split(Kb, Ksh, Ksl, S_LEN * GS_DIM);
    split(Vb, Vsh, Vsl, S_LEN * GS_DIM);

    // MMA flash attention
    attn_mma_kernel<<<dim3(S_LEN / QT, N_HEAD), 256, smem_attn>>>(
        Qsh, Qsl, Ksh, Ksl, Vsh, Vsl, AOb);

    // Output projection
    split(Wo, Woh, Wol, D_MODEL * D_MODEL);
    split(AOb, AOh, AOl, S_LEN * D_MODEL);
    gemm_mma_kernel<<<dim3(D_MODEL / BN, S_LEN / BM), 256>>>(
        AOh, AOl, Woh, Wol, bo, out, S_LEN, D_MODEL, D_MODEL);
}

// round 11
// speedup vs baseline: 3.1893x; 1.6020x over previous
#include <cuda_runtime.h>
#include <cuda_bf16.h>
#include <math.h>
#include <stdint.h>

// ---------------------------------------------------------------------------
// Problem constants (B=1, S=2048, D=4096, n_head=32, kv_head=8, hd=128)
// ---------------------------------------------------------------------------
#define S_LEN 2048
#define D_MODEL 4096
#define GS_DIM 1024
#define N_HEAD 32
#define KV_HEAD 8
#define HEAD_DIM 128
#define GVS 64

// fp32 scratch
__device__ float g_Q[S_LEN * D_MODEL];
__device__ float g_K[S_LEN * GS_DIM];
__device__ float g_V[S_LEN * GS_DIM];
__device__ float2 g_tab[S_LEN * GVS];

// bf16 hi/lo splits
__device__ __nv_bfloat16 g_xh[S_LEN * D_MODEL],  g_xl[S_LEN * D_MODEL];
__device__ __nv_bfloat16 g_yh[S_LEN * D_MODEL],  g_yl[S_LEN * D_MODEL];
__device__ __nv_bfloat16 g_Wqh[D_MODEL * D_MODEL], g_Wql[D_MODEL * D_MODEL];
__device__ __nv_bfloat16 g_Wkh[D_MODEL * GS_DIM],  g_Wkl[D_MODEL * GS_DIM];
__device__ __nv_bfloat16 g_Wvh[D_MODEL * GS_DIM],  g_Wvl[D_MODEL * GS_DIM];
__device__ __nv_bfloat16 g_Woh[D_MODEL * D_MODEL], g_Wol[D_MODEL * D_MODEL];
__device__ __nv_bfloat16 g_AOh[S_LEN * D_MODEL],   g_AOl[S_LEN * D_MODEL];
__device__ __nv_bfloat16 g_Qh[S_LEN * D_MODEL],    g_Ql[S_LEN * D_MODEL];
__device__ __nv_bfloat16 g_Kh[S_LEN * GS_DIM],     g_Kl[S_LEN * GS_DIM];
__device__ __nv_bfloat16 g_Vh[S_LEN * GS_DIM],     g_Vl[S_LEN * GS_DIM];

// ---------------------------------------------------------------------------
// helpers
// ---------------------------------------------------------------------------
__global__ void split_kernel(const float* __restrict__ src,
                             __nv_bfloat16* __restrict__ hi,
                             __nv_bfloat16* __restrict__ lo, int n, float scale)
{
    int i = blockIdx.x * blockDim.x + threadIdx.x;
    if (i >= n) return;
    float v = src[i] * scale;
    __nv_bfloat16 h = __float2bfloat16(v);
    hi[i] = h;
    lo[i] = __float2bfloat16(v - __bfloat162float(h));
}

__device__ __forceinline__ void ldmx4(uint32_t* r, const void* p)
{
    uint32_t a = (uint32_t)__cvta_generic_to_shared(p);
    asm volatile("ldmatrix.sync.aligned.m8n8.x4.shared.b16 {%0,%1,%2,%3}, [%4];"
                 : "=r"(r[0]), "=r"(r[1]), "=r"(r[2]), "=r"(r[3]) : "r"(a));
}
__device__ __forceinline__ void ldmx4t(uint32_t* r, const void* p)
{
    uint32_t a = (uint32_t)__cvta_generic_to_shared(p);
    asm volatile("ldmatrix.sync.aligned.m8n8.x4.trans.shared.b16 {%0,%1,%2,%3}, [%4];"
                 : "=r"(r[0]), "=r"(r[1]), "=r"(r[2]), "=r"(r[3]) : "r"(a));
}
__device__ __forceinline__ void mma16816(float* d, const uint32_t* a,
                                         uint32_t b0, uint32_t b1)
{
    asm volatile(
        "mma.sync.aligned.m16n8k16.row.col.f32.bf16.bf16.f32 "
        "{%0,%1,%2,%3}, {%4,%5,%6,%7}, {%8,%9}, {%0,%1,%2,%3};"
        : "+f"(d[0]), "+f"(d[1]), "+f"(d[2]), "+f"(d[3])
        : "r"(a[0]), "r"(a[1]), "r"(a[2]), "r"(a[3]), "r"(b0), "r"(b1));
}
__device__ __forceinline__ void cpasync16(void* smem, const void* gmem)
{
    uint32_t a = (uint32_t)__cvta_generic_to_shared(smem);
    asm volatile("cp.async.cg.shared.global [%0], [%1], 16;" :: "r"(a), "l"(gmem));
}
#define CP_COMMIT() asm volatile("cp.async.commit_group;")
#define CP_WAIT1()  asm volatile("cp.async.wait_group 1;")

// ---------------------------------------------------------------------------
// Split-bf16 3-pass GEMM, double-buffered with cp.async.
// CTA 128x128, BK=32, 8 warps of 64x32. Dynamic smem, 2 stages.
// A-tile staging (FIXED from R10): each thread loads 2 chunks of 8 bf16 from
// the SAME row (tid>>1), column halves (tid&1)*8 and (tid&1)*8+16.
// ---------------------------------------------------------------------------
#define BM 128
#define BN 128
#define BK 32
#define A_STRIDE 40
#define B_STRIDE 136
#define ASZ (BM * A_STRIDE)
#define BSZ (BK * B_STRIDE)
#define STG (2 * ASZ + 2 * BSZ)
#define GEMM_SMEM (2 * STG * 2)   // bytes

__global__ __launch_bounds__(256) void gemm_mma_kernel(
    const __nv_bfloat16* __restrict__ Ah, const __nv_bfloat16* __restrict__ Al,
    const __nv_bfloat16* __restrict__ Bh, const __nv_bfloat16* __restrict__ Bl,
    const float* __restrict__ bias, float* __restrict__ C,
    int M, int N, int K)
{
    extern __shared__ __nv_bfloat16 sm[];

    const int tid  = threadIdx.x;
    const int lane = tid & 31;
    const int wid  = tid >> 5;
    const int wm   = (wid >> 2) * 64;
    const int wn   = (wid & 3) * 32;
    const int m0   = blockIdx.y * BM;
    const int n0   = blockIdx.x * BN;

    // prefetch chunk indices (16B = 8 bf16 per cp.async)
    const int ar = tid >> 1;                 // A row 0..127
    const int ac = (tid & 1) * 8;            // A col chunk 0 or 8 (then +16)
    const int br0 = tid >> 4, bc0 = (tid & 15) * 8;          // B rows 0..15
    const int br1 = br0 + 16, bc1 = bc0;                     // B rows 16..31

    float acc[4][4][4];
#pragma unroll
    for (int i = 0; i < 4; i++)
#pragma unroll
        for (int j = 0; j < 4; j++)
#pragma unroll
            for (int v = 0; v < 4; v++) acc[i][j][v] = 0.0f;

#define PREFETCH(st, k0)                                                          \
    do {                                                                          \
        __nv_bfloat16* aH = sm + (st) * STG;                                      \
        __nv_bfloat16* aL = aH + ASZ;                                             \
        __nv_bfloat16* bH = aL + ASZ;                                             \
        __nv_bfloat16* bL = bH + BSZ;                                             \
        const __nv_bfloat16* gah = Ah + (size_t)(m0 + ar) * K + (k0) + ac;        \
        const __nv_bfloat16* gal = Al + (size_t)(m0 + ar) * K + (k0) + ac;        \
        cpasync16(aH + ar * A_STRIDE + ac,      gah);                             \
        cpasync16(aH + ar * A_STRIDE + ac + 16, gah + 16);                        \
        cpasync16(aL + ar * A_STRIDE + ac,      gal);                             \
        cpasync16(aL + ar * A_STRIDE + ac + 16, gal + 16);                        \
        cpasync16(bH + br0 * B_STRIDE + bc0, Bh + (size_t)((k0) + br0) * N + n0 + bc0); \
        cpasync16(bH + br1 * B_STRIDE + bc1, Bh + (size_t)((k0) + br1) * N + n0 + bc1); \
        cpasync16(bL + br0 * B_STRIDE + bc0, Bl + (size_t)((k0) + br0) * N + n0 + bc0); \
        cpasync16(bL + br1 * B_STRIDE + bc1, Bl + (size_t)((k0) + br1) * N + n0 + bc1); \
    } while (0)

    const int nk = K / BK;
    PREFETCH(0, 0);
    CP_COMMIT();

    const int lrow = lane & 15;
    const int lcol = (lane >> 4) * 8;

    for (int i = 0; i < nk; i++) {
        if (i + 1 < nk) PREFETCH((i + 1) & 1, (i + 1) * BK);
        CP_COMMIT();
        CP_WAIT1();
        __syncthreads();

        const int st = i & 1;
        __nv_bfloat16* aH = sm + st * STG;
        __nv_bfloat16* aL = aH + ASZ;
        __nv_bfloat16* bH = aL + ASZ;
        __nv_bfloat16* bL = bH + BSZ;

#pragma unroll
        for (int kk = 0; kk < BK; kk += 16) {
            uint32_t ah[4][4], al[4][4], bh[2][4], bl[2][4];
#pragma unroll
            for (int mt = 0; mt < 4; mt++) {
                ldmx4(ah[mt], aH + (wm + mt * 16 + lrow) * A_STRIDE + kk + lcol);
                ldmx4(al[mt], aL + (wm + mt * 16 + lrow) * A_STRIDE + kk + lcol);
            }
#pragma unroll
            for (int ntp = 0; ntp < 2; ntp++) {
                ldmx4t(bh[ntp], bH + (kk + lrow) * B_STRIDE + wn + ntp * 16 + lcol);
                ldmx4t(bl[ntp], bL + (kk + lrow) * B_STRIDE + wn + ntp * 16 + lcol);
            }
#pragma unroll
            for (int mt = 0; mt < 4; mt++)
#pragma unroll
                for (int nt = 0; nt < 4; nt++) {
                    const int ntp = nt >> 1, off = (nt & 1) * 2;
                    mma16816(acc[mt][nt], ah[mt], bh[ntp][off], bh[ntp][off + 1]);
                    mma16816(acc[mt][nt], ah[mt], bl[ntp][off], bl[ntp][off + 1]);
                    mma16816(acc[mt][nt], al[mt], bh[ntp][off], bh[ntp][off + 1]);
                }
        }
        __syncthreads();
    }
#undef PREFETCH

    const int er = lane >> 2;
    const int ec = (lane & 3) * 2;
#pragma unroll
    for (int mt = 0; mt < 4; mt++)
#pragma unroll
        for (int nt = 0; nt < 4; nt++) {
            int r0 = m0 + wm + mt * 16 + er;
            int c0 = n0 + wn + nt * 8 + ec;
            float b0 = bias[c0], b1 = bias[c0 + 1];
            float2 v0 = make_float2(acc[mt][nt][0] + b0, acc[mt][nt][1] + b1);
            float2 v1 = make_float2(acc[mt][nt][2] + b0, acc[mt][nt][3] + b1);
            *(float2*)(C + (size_t)r0 * N + c0) = v0;
            *(float2*)(C + (size_t)(r0 + 8) * N + c0) = v1;
        }
}

// ---------------------------------------------------------------------------
// RoPE: table, then fused apply+split (emits bf16 hi/lo directly, scale folded)
// ---------------------------------------------------------------------------
__global__ void rope_table_kernel()
{
    int idx = blockIdx.x * blockDim.x + threadIdx.x;
    if (idx >= S_LEN * GVS) return;
    int s = idx / GVS, i = idx % GVS;
    double phi = exp(-((double)i / (double)GVS) * log(5000.0));
    double sn, c;
    sincos((double)s * phi, &sn, &c);   // sin first, cos second
    g_tab[idx] = make_float2((float)c, (float)sn);
}

__global__ void rope_split_kernel(const float* __restrict__ T, int H,
                                  __nv_bfloat16* __restrict__ hi,
                                  __nv_bfloat16* __restrict__ lo, float scale)
{
    int idx = blockIdx.x * blockDim.x + threadIdx.x;
    int total = S_LEN * H * GVS;
    if (idx >= total) return;
    int i = idx % GVS;
    int h = (idx / GVS) % H;
    int s = idx / (GVS * H);
    float2 cs = g_tab[s * GVS + i];
    size_t base = ((size_t)s * H + h) * HEAD_DIM + 2 * i;
    float tr = T[base], ti = T[base + 1];
    float ro = (tr * cs.x - ti * cs.y) * scale;
    float io = (tr * cs.y + ti * cs.x) * scale;
    __nv_bfloat16 h0 = __float2bfloat16(ro);
    __nv_bfloat16 h1 = __float2bfloat16(io);
    hi[base]     = h0;
    hi[base + 1] = h1;
    lo[base]     = __float2bfloat16(ro - __bfloat162float(h0));
    lo[base + 1] = __float2bfloat16(io - __bfloat162float(h1));
}

// ---------------------------------------------------------------------------
// MMA flash attention (epilogue emits split bf16 AO directly)
// ---------------------------------------------------------------------------
#define QT 128
#define KT 64
#define DSTR 136
#define PSTR 72

__global__ __launch_bounds__(256) void attn_mma_kernel(
    const __nv_bfloat16* __restrict__ Qh, const __nv_bfloat16* __restrict__ Ql,
    const __nv_bfloat16* __restrict__ Kh, const __nv_bfloat16* __restrict__ Kl,
    const __nv_bfloat16* __restrict__ Vh, const __nv_bfloat16* __restrict__ Vl,
    __nv_bfloat16* __restrict__ Oh, __nv_bfloat16* __restrict__ Ol)
{
    extern __shared__ __nv_bfloat16 sb[];
    __nv_bfloat16* sQh = sb;
    __nv_bfloat16* sQl = sQh + QT * DSTR;
    __nv_bfloat16* sKh = sQl + QT * DSTR;
    __nv_bfloat16* sKl = sKh + KT * DSTR;
    __nv_bfloat16* sVh = sKl + KT * DSTR;
    __nv_bfloat16* sVl = sVh + KT * DSTR;
    __nv_bfloat16* sPh = sVl + KT * DSTR;
    __nv_bfloat16* sPl = sPh + QT * PSTR;

    const int tid  = threadIdx.x;
    const int lane = tid & 31;
    const int wid  = tid >> 5;
    const int wrow = wid * 16;
    const int qt   = blockIdx.x;
    const int h    = blockIdx.y;
    const int q0   = qt * QT;
    const int kvh  = h >> 2;

    for (int t = tid; t < QT * 16; t += 256) {
        int r = t >> 4, c8 = (t & 15) * 8;
        const uint4* ph = (const uint4*)(Qh + (size_t)(q0 + r) * D_MODEL + h * HEAD_DIM + c8);
        const uint4* pl = (const uint4*)(Ql + (size_t)(q0 + r) * D_MODEL + h * HEAD_DIM + c8);
        *(uint4*)(sQh + r * DSTR + c8) = *ph;
        *(uint4*)(sQl + r * DSTR + c8) = *pl;
    }

    float oacc[16][4];
#pragma unroll
    for (int nt = 0; nt < 16; nt++)
#pragma unroll
        for (int v = 0; v < 4; v++) oacc[nt][v] = 0.0f;
    float m_lo = -1e30f, m_hi = -1e30f, l_lo = 0.0f, l_hi = 0.0f;

    const int lrow = lane & 15;
    const int lcol = (lane >> 4) * 8;
    const int er   = lane >> 2;
    const int ec   = (lane & 3) * 2;

    const int ktmax = 2 * qt + 1;
    for (int kt = 0; kt <= ktmax; kt++) {
        const int k0 = kt * KT;
        __syncthreads();
        for (int t = tid; t < KT * 16; t += 256) {
            int r = t >> 4, c8 = (t & 15) * 8;
            size_t g = (size_t)(k0 + r) * GS_DIM + kvh * HEAD_DIM + c8;
            *(uint4*)(sKh + r * DSTR + c8) = *(const uint4*)(Kh + g);
            *(uint4*)(sKl + r * DSTR + c8) = *(const uint4*)(Kl + g);
            *(uint4*)(sVh + r * DSTR + c8) = *(const uint4*)(Vh + g);
            *(uint4*)(sVl + r * DSTR + c8) = *(const uint4*)(Vl + g);
        }
        __syncthreads();

        if (k0 > q0 + wrow + 15) continue;

        float sacc[8][4];
#pragma unroll
        for (int nt = 0; nt < 8; nt++)
#pragma unroll
            for (int v = 0; v < 4; v++) sacc[nt][v] = 0.0f;

#pragma unroll
        for (int kk = 0; kk < 8; kk++) {
            uint32_t ah[4], al[4];
            ldmx4(ah, sQh + (wrow + lrow) * DSTR + kk * 16 + lcol);
            ldmx4(al, sQl + (wrow + lrow) * DSTR + kk * 16 + lcol);
#pragma unroll
            for (int np = 0; np < 4; np++) {
                uint32_t bh[4], bl[4];
                ldmx4(bh, sKh + (np * 16 + lrow) * DSTR + kk * 16 + lcol);
                ldmx4(bl, sKl + (np * 16 + lrow) * DSTR + kk * 16 + lcol);
                mma16816(sacc[2 * np],     ah, bh[0], bh[2]);
                mma16816(sacc[2 * np],     ah, bl[0], bl[2]);
                mma16816(sacc[2 * np],     al, bh[0], bh[2]);
                mma16816(sacc[2 * np + 1], ah, bh[1], bh[3]);
                mma16816(sacc[2 * np + 1], ah, bl[1], bl[3]);
                mma16816(sacc[2 * np + 1], al, bh[1], bh[3]);
            }
        }

        if (kt >= 2 * qt) {
            int gq_lo = q0 + wrow + er;
            int gq_hi = gq_lo + 8;
#pragma unroll
            for (int nt = 0; nt < 8; nt++) {
                int c0 = k0 + nt * 8 + ec;
                if (c0 > gq_lo)     sacc[nt][0] = -1e30f;
                if (c0 + 1 > gq_lo) sacc[nt][1] = -1e30f;
                if (c0 > gq_hi)     sacc[nt][2] = -1e30f;
                if (c0 + 1 > gq_hi) sacc[nt][3] = -1e30f;
            }
        }

        float mx_lo = -1e30f, mx_hi = -1e30f;
#pragma unroll
        for (int nt = 0; nt < 8; nt++) {
            mx_lo = fmaxf(mx_lo, fmaxf(sacc[nt][0], sacc[nt][1]));
            mx_hi = fmaxf(mx_hi, fmaxf(sacc[nt][2], sacc[nt][3]));
        }
        mx_lo = fmaxf(mx_lo, __shfl_xor_sync(0xffffffffu, mx_lo, 1));
        mx_lo = fmaxf(mx_lo, __shfl_xor_sync(0xffffffffu, mx_lo, 2));
        mx_hi = fmaxf(mx_hi, __shfl_xor_sync(0xffffffffu, mx_hi, 1));
        mx_hi = fmaxf(mx_hi, __shfl_xor_sync(0xffffffffu, mx_hi, 2));

        float mn_lo = fmaxf(m_lo, mx_lo);
        float mn_hi = fmaxf(m_hi, mx_hi);
        float al_lo = __expf(m_lo - mn_lo);
        float al_hi = __expf(m_hi - mn_hi);

        float sum_lo = 0.0f, sum_hi = 0.0f;
#pragma unroll
        for (int nt = 0; nt < 8; nt++) {
            float p0 = __expf(sacc[nt][0] - mn_lo);
            float p1 = __expf(sacc[nt][1] - mn_lo);
            float p2 = __expf(sacc[nt][2] - mn_hi);
            float p3 = __expf(sacc[nt][3] - mn_hi);
            sum_lo += p0 + p1;
            sum_hi += p2 + p3;
            int c = nt * 8 + ec;
            __nv_bfloat16 h0 = __float2bfloat16(p0);
            __nv_bfloat16 h1 = __float2bfloat16(p1);
            __nv_bfloat16 h2 = __float2bfloat16(p2);
            __nv_bfloat16 h3 = __float2bfloat16(p3);
            sPh[(wrow + er) * PSTR + c]     = h0;
            sPh[(wrow + er) * PSTR + c + 1] = h1;
            sPh[(wrow + er + 8) * PSTR + c]     = h2;
            sPh[(wrow + er + 8) * PSTR + c + 1] = h3;
            sPl[(wrow + er) * PSTR + c]     = __float2bfloat16(p0 - __bfloat162float(h0));
            sPl[(wrow + er) * PSTR + c + 1] = __float2bfloat16(p1 - __bfloat162float(h1));
            sPl[(wrow + er + 8) * PSTR + c]     = __float2bfloat16(p2 - __bfloat162float(h2));
            sPl[(wrow + er + 8) * PSTR + c + 1] = __float2bfloat16(p3 - __bfloat162float(h3));
        }
        sum_lo += __shfl_xor_sync(0xffffffffu, sum_lo, 1);
        sum_lo += __shfl_xor_sync(0xffffffffu, sum_lo, 2);
        sum_hi += __shfl_xor_sync(0xffffffffu, sum_hi, 1);
        sum_hi += __shfl_xor_sync(0xffffffffu, sum_hi, 2);

        l_lo = l_lo * al_lo + sum_lo;
        l_hi = l_hi * al_hi + sum_hi;
        m_lo = mn_lo; m_hi = mn_hi;

#pragma unroll
        for (int nt = 0; nt < 16; nt++) {
            oacc[nt][0] *= al_lo; oacc[nt][1] *= al_lo;
            oacc[nt][2] *= al_hi; oacc[nt][3] *= al_hi;
        }
        __syncwarp();

#pragma unroll
        for (int kk = 0; kk < 4; kk++) {
            uint32_t ah[4], al2[4];
            ldmx4(ah,  sPh + (wrow + lrow) * PSTR + kk * 16 + lcol);
            ldmx4(al2, sPl + (wrow + lrow) * PSTR + kk * 16 + lcol);
#pragma unroll
            for (int np = 0; np < 8; np++) {
                uint32_t bh[4], bl[4];
                ldmx4t(bh, sVh + (kk * 16 + lrow) * DSTR + np * 16 + lcol);
                ldmx4t(bl, sVl + (kk * 16 + lrow) * DSTR + np * 16 + lcol);
                mma16816(oacc[2 * np],     ah,  bh[0], bh[1]);
                mma16816(oacc[2 * np],     al2, bh[0], bh[1]);
                mma16816(oacc[2 * np],     ah,  bl[0], bl[1]);
                mma16816(oacc[2 * np + 1], ah,  bh[2], bh[3]);
                mma16816(oacc[2 * np + 1], al2, bh[2], bh[3]);
                mma16816(oacc[2 * np + 1], ah,  bl[2], bl[3]);
            }
        }
    }

    float inv_lo = 1.0f / l_lo;
    float inv_hi = 1.0f / l_hi;
    int gq_lo = q0 + wrow + er;
#pragma unroll
    for (int nt = 0; nt < 16; nt++) {
        int c = h * HEAD_DIM + nt * 8 + ec;
        float v0 = oacc[nt][0] * inv_lo, v1 = oacc[nt][1] * inv_lo;
        float v2 = oacc[nt][2] * inv_hi, v3 = oacc[nt][3] * inv_hi;
        __nv_bfloat16 h0 = __float2bfloat16(v0), h1 = __float2bfloat16(v1);
        __nv_bfloat16 h2 = __float2bfloat16(v2), h3 = __float2bfloat16(v3);
        __nv_bfloat162* p;
        p = (__nv_bfloat162*)(Oh + (size_t)gq_lo * D_MODEL + c);
        *p = __nv_bfloat162(h0, h1);
        p = (__nv_bfloat162*)(Oh + (size_t)(gq_lo + 8) * D_MODEL + c);
        *p = __nv_bfloat162(h2, h3);
        p = (__nv_bfloat162*)(Ol + (size_t)gq_lo * D_MODEL + c);
        *p = __nv_bfloat162(__float2bfloat16(v0 - __bfloat162float(h0)),
                            __float2bfloat16(v1 - __bfloat162float(h1)));
        p = (__nv_bfloat162*)(Ol + (size_t)(gq_lo + 8) * D_MODEL + c);
        *p = __nv_bfloat162(__float2bfloat16(v2 - __bfloat162float(h2)),
                            __float2bfloat16(v3 - __bfloat162float(h3)));
    }
}

// ---------------------------------------------------------------------------
// Launch. Input order (R6-confirmed dict order):
//   0:x 1:y 2:Wq 3:bq 4:Wk 5:bk 6:Wv 7:bv 8:Wo 9:bo
// ---------------------------------------------------------------------------
static inline void split(const float* s, __nv_bfloat16* h, __nv_bfloat16* l,
                         int n, float scale = 1.0f)
{
    split_kernel<<<(n + 255) / 256, 256>>>(s, h, l, n, scale);
}

extern "C" void kernel_launch(void* const* d_in, const int* in_sizes, int n_in,
                              void* d_out, int out_size)
{
    (void)in_sizes; (void)n_in; (void)out_size;
    const float* x  = (const float*)d_in[0];
    const float* y  = (const float*)d_in[1];
    const float* Wq = (const float*)d_in[2];
    const float* bq = (const float*)d_in[3];
    const float* Wk = (const float*)d_in[4];
    const float* bk = (const float*)d_in[5];
    const float* Wv = (const float*)d_in[6];
    const float* bv = (const float*)d_in[7];
    const float* Wo = (const float*)d_in[8];
    const float* bo = (const float*)d_in[9];
    float* out = (float*)d_out;

    float *Qb, *Kb, *Vb;
    cudaGetSymbolAddress((void**)&Qb, g_Q);
    cudaGetSymbolAddress((void**)&Kb, g_K);
    cudaGetSymbolAddress((void**)&Vb, g_V);

    __nv_bfloat16 *xh, *xl, *yh, *yl, *Wqh, *Wql, *Wkh, *Wkl, *Wvh, *Wvl,
                  *Woh, *Wol, *AOh, *AOl, *Qsh, *Qsl, *Ksh, *Ksl, *Vsh, *Vsl;
    cudaGetSymbolAddress((void**)&xh, g_xh);   cudaGetSymbolAddress((void**)&xl, g_xl);
    cudaGetSymbolAddress((void**)&yh, g_yh);   cudaGetSymbolAddress((void**)&yl, g_yl);
    cudaGetSymbolAddress((void**)&Wqh, g_Wqh); cudaGetSymbolAddress((void**)&Wql, g_Wql);
    cudaGetSymbolAddress((void**)&Wkh, g_Wkh); cudaGetSymbolAddress((void**)&Wkl, g_Wkl);
    cudaGetSymbolAddress((void**)&Wvh, g_Wvh); cudaGetSymbolAddress((void**)&Wvl, g_Wvl);
    cudaGetSymbolAddress((void**)&Woh, g_Woh); cudaGetSymbolAddress((void**)&Wol, g_Wol);
    cudaGetSymbolAddress((void**)&AOh, g_AOh); cudaGetSymbolAddress((void**)&AOl, g_AOl);
    cudaGetSymbolAddress((void**)&Qsh, g_Qh);  cudaGetSymbolAddress((void**)&Qsl, g_Ql);
    cudaGetSymbolAddress((void**)&Ksh, g_Kh);  cudaGetSymbolAddress((void**)&Ksl, g_Kl);
    cudaGetSymbolAddress((void**)&Vsh, g_Vh);  cudaGetSymbolAddress((void**)&Vsl, g_Vl);

    cudaFuncSetAttribute(gemm_mma_kernel, cudaFuncAttributeMaxDynamicSharedMemorySize, GEMM_SMEM);
    const int smem_attn = (2 * QT * DSTR + 4 * KT * DSTR + 2 * QT * PSTR) * 2;
    cudaFuncSetAttribute(attn_mma_kernel, cudaFuncAttributeMaxDynamicSharedMemorySize, smem_attn);

    // Projections (double-buffered MMA GEMMs)
    split(x, xh, xl, S_LEN * D_MODEL);
    split(Wq, Wqh, Wql, D_MODEL * D_MODEL);
    gemm_mma_kernel<<<dim3(D_MODEL / BN, S_LEN / BM), 256, GEMM_SMEM>>>(
        xh, xl, Wqh, Wql, bq, Qb, S_LEN, D_MODEL, D_MODEL);
    split(y, yh, yl, S_LEN * D_MODEL);
    split(Wk, Wkh, Wkl, D_MODEL * GS_DIM);
    gemm_mma_kernel<<<dim3(GS_DIM / BN, S_LEN / BM), 256, GEMM_SMEM>>>(
        yh, yl, Wkh, Wkl, bk, Kb, S_LEN, GS_DIM, D_MODEL);
    split(Wv, Wvh, Wvl, D_MODEL * GS_DIM);
    gemm_mma_kernel<<<dim3(GS_DIM / BN, S_LEN / BM), 256, GEMM_SMEM>>>(
        yh, yl, Wvh, Wvl, bv, Vb, S_LEN, GS_DIM, D_MODEL);

    // RoPE: table once, then fused rotate+split (Q gets softmax scale folded)
    rope_table_kernel<<<(S_LEN * GVS + 255) / 256, 256>>>();
    rope_split_kernel<<<(S_LEN * N_HEAD * GVS + 255) / 256, 256>>>(
        Qb, N_HEAD, Qsh, Qsl, 0.08838834764831845f);
    rope_split_kernel<<<(S_LEN * KV_HEAD * GVS + 255) / 256, 256>>>(
        Kb, KV_HEAD, Ksh, Ksl, 1.0f);
    split(Vb, Vsh, Vsl, S_LEN * GS_DIM);

    // MMA flash attention -> split bf16 AO directly
    attn_mma_kernel<<<dim3(S_LEN / QT, N_HEAD), 256, smem_attn>>>(
        Qsh, Qsl, Ksh, Ksl, Vsh, Vsl, AOh, AOl);

    // Output projection
    split(Wo, Woh, Wol, D_MODEL * D_MODEL);
    gemm_mma_kernel<<<dim3(D_MODEL / BN, S_LEN / BM), 256, GEMM_SMEM>>>(
        AOh, AOl, Woh, Wol, bo, out, S_LEN, D_MODEL, D_MODEL);
}

// round 12
// speedup vs baseline: 3.2223x; 1.0103x over previous
#include <cuda_runtime.h>
#include <cuda_bf16.h>
#include <math.h>
#include <stdint.h>

// ---------------------------------------------------------------------------
// Problem constants (B=1, S=2048, D=4096, n_head=32, kv_head=8, hd=128)
// ---------------------------------------------------------------------------
#define S_LEN 2048
#define D_MODEL 4096
#define GS_DIM 1024
#define N_HEAD 32
#define KV_HEAD 8
#define HEAD_DIM 128
#define GVS 64

// fp32 scratch
__device__ float g_Q[S_LEN * D_MODEL];
__device__ float g_K[S_LEN * GS_DIM];
__device__ float2 g_tab[S_LEN * GVS];

// bf16 hi/lo splits
__device__ __nv_bfloat16 g_xh[S_LEN * D_MODEL],  g_xl[S_LEN * D_MODEL];
__device__ __nv_bfloat16 g_yh[S_LEN * D_MODEL],  g_yl[S_LEN * D_MODEL];
__device__ __nv_bfloat16 g_Wqh[D_MODEL * D_MODEL], g_Wql[D_MODEL * D_MODEL];
__device__ __nv_bfloat16 g_Wkh[D_MODEL * GS_DIM],  g_Wkl[D_MODEL * GS_DIM];
__device__ __nv_bfloat16 g_Wvh[D_MODEL * GS_DIM],  g_Wvl[D_MODEL * GS_DIM];
__device__ __nv_bfloat16 g_Woh[D_MODEL * D_MODEL], g_Wol[D_MODEL * D_MODEL];
__device__ __nv_bfloat16 g_AOh[S_LEN * D_MODEL],   g_AOl[S_LEN * D_MODEL];
__device__ __nv_bfloat16 g_Qh[S_LEN * D_MODEL],    g_Ql[S_LEN * D_MODEL];
__device__ __nv_bfloat16 g_Kh[S_LEN * GS_DIM],     g_Kl[S_LEN * GS_DIM];
__device__ __nv_bfloat16 g_Vh[S_LEN * GS_DIM],     g_Vl[S_LEN * GS_DIM];

// ---------------------------------------------------------------------------
// Mega-split: all 6 fp32->bf16 hi/lo conversions in one launch
// ---------------------------------------------------------------------------
struct SplitArgs {
    const float* src[6];
    __nv_bfloat16* hi[6];
    __nv_bfloat16* lo[6];
    int off[7];   // prefix sums, off[6] = total
};

__global__ void mega_split_kernel(SplitArgs a)
{
    int i = blockIdx.x * blockDim.x + threadIdx.x;
    if (i >= a.off[6]) return;
    int s = 0;
#pragma unroll
    for (int t = 1; t < 6; t++) s += (i >= a.off[t]);
    int j = i - a.off[s];
    float v = a.src[s][j];
    __nv_bfloat16 h = __float2bfloat16(v);
    a.hi[s][j] = h;
    a.lo[s][j] = __float2bfloat16(v - __bfloat162float(h));
}

// ---------------------------------------------------------------------------
// MMA helpers
// ---------------------------------------------------------------------------
__device__ __forceinline__ void ldmx4(uint32_t* r, const void* p)
{
    uint32_t a = (uint32_t)__cvta_generic_to_shared(p);
    asm volatile("ldmatrix.sync.aligned.m8n8.x4.shared.b16 {%0,%1,%2,%3}, [%4];"
                 : "=r"(r[0]), "=r"(r[1]), "=r"(r[2]), "=r"(r[3]) : "r"(a));
}
__device__ __forceinline__ void ldmx4t(uint32_t* r, const void* p)
{
    uint32_t a = (uint32_t)__cvta_generic_to_shared(p);
    asm volatile("ldmatrix.sync.aligned.m8n8.x4.trans.shared.b16 {%0,%1,%2,%3}, [%4];"
                 : "=r"(r[0]), "=r"(r[1]), "=r"(r[2]), "=r"(r[3]) : "r"(a));
}
__device__ __forceinline__ void mma16816(float* d, const uint32_t* a,
                                         uint32_t b0, uint32_t b1)
{
    asm volatile(
        "mma.sync.aligned.m16n8k16.row.col.f32.bf16.bf16.f32 "
        "{%0,%1,%2,%3}, {%4,%5,%6,%7}, {%8,%9}, {%0,%1,%2,%3};"
        : "+f"(d[0]), "+f"(d[1]), "+f"(d[2]), "+f"(d[3])
        : "r"(a[0]), "r"(a[1]), "r"(a[2]), "r"(a[3]), "r"(b0), "r"(b1));
}
__device__ __forceinline__ void cpasync16(void* smem, const void* gmem)
{
    uint32_t a = (uint32_t)__cvta_generic_to_shared(smem);
    asm volatile("cp.async.cg.shared.global [%0], [%1], 16;" :: "r"(a), "l"(gmem));
}
#define CP_COMMIT() asm volatile("cp.async.commit_group;")
#define CP_WAIT1()  asm volatile("cp.async.wait_group 1;")

// ---------------------------------------------------------------------------
// Split-bf16 3-pass GEMM tile body (double-buffered cp.async).
// Output: fp32 (C) or split bf16 (Ch/Cl) when C == nullptr.
// ---------------------------------------------------------------------------
#define BM 128
#define BN 128
#define BK 32
#define A_STRIDE 40
#define B_STRIDE 136
#define ASZ (BM * A_STRIDE)
#define BSZ (BK * B_STRIDE)
#define STG (2 * ASZ + 2 * BSZ)
#define GEMM_SMEM (2 * STG * 2)   // bytes

__device__ __forceinline__ void gemm_tile(
    const __nv_bfloat16* __restrict__ Ah, const __nv_bfloat16* __restrict__ Al,
    const __nv_bfloat16* __restrict__ Bh, const __nv_bfloat16* __restrict__ Bl,
    const float* __restrict__ bias,
    float* __restrict__ C, __nv_bfloat16* __restrict__ Ch,
    __nv_bfloat16* __restrict__ Cl,
    int N, int K, int m0, int n0, __nv_bfloat16* sm)
{
    const int tid  = threadIdx.x;
    const int lane = tid & 31;
    const int wid  = tid >> 5;
    const int wm   = (wid >> 2) * 64;
    const int wn   = (wid & 3) * 32;

    const int ar = tid >> 1;
    const int ac = (tid & 1) * 8;
    const int br0 = tid >> 4, bc0 = (tid & 15) * 8;
    const int br1 = br0 + 16, bc1 = bc0;

    float acc[4][4][4];
#pragma unroll
    for (int i = 0; i < 4; i++)
#pragma unroll
        for (int j = 0; j < 4; j++)
#pragma unroll
            for (int v = 0; v < 4; v++) acc[i][j][v] = 0.0f;

#define PREFETCH(st, k0)                                                          \
    do {                                                                          \
        __nv_bfloat16* aH = sm + (st) * STG;                                      \
        __nv_bfloat16* aL = aH + ASZ;                                             \
        __nv_bfloat16* bH = aL + ASZ;                                             \
        __nv_bfloat16* bL = bH + BSZ;                                             \
        const __nv_bfloat16* gah = Ah + (size_t)(m0 + ar) * K + (k0) + ac;        \
        const __nv_bfloat16* gal = Al + (size_t)(m0 + ar) * K + (k0) + ac;        \
        cpasync16(aH + ar * A_STRIDE + ac,      gah);                             \
        cpasync16(aH + ar * A_STRIDE + ac + 16, gah + 16);                        \
        cpasync16(aL + ar * A_STRIDE + ac,      gal);                             \
        cpasync16(aL + ar * A_STRIDE + ac + 16, gal + 16);                        \
        cpasync16(bH + br0 * B_STRIDE + bc0, Bh + (size_t)((k0) + br0) * N + n0 + bc0); \
        cpasync16(bH + br1 * B_STRIDE + bc1, Bh + (size_t)((k0) + br1) * N + n0 + bc1); \
        cpasync16(bL + br0 * B_STRIDE + bc0, Bl + (size_t)((k0) + br0) * N + n0 + bc0); \
        cpasync16(bL + br1 * B_STRIDE + bc1, Bl + (size_t)((k0) + br1) * N + n0 + bc1); \
    } while (0)

    const int nk = K / BK;
    PREFETCH(0, 0);
    CP_COMMIT();

    const int lrow = lane & 15;
    const int lcol = (lane >> 4) * 8;

    for (int i = 0; i < nk; i++) {
        if (i + 1 < nk) PREFETCH((i + 1) & 1, (i + 1) * BK);
        CP_COMMIT();
        CP_WAIT1();
        __syncthreads();

        const int st = i & 1;
        __nv_bfloat16* aH = sm + st * STG;
        __nv_bfloat16* aL = aH + ASZ;
        __nv_bfloat16* bH = aL + ASZ;
        __nv_bfloat16* bL = bH + BSZ;

#pragma unroll
        for (int kk = 0; kk < BK; kk += 16) {
            uint32_t ah[4][4], al[4][4], bh[2][4], bl[2][4];
#pragma unroll
            for (int mt = 0; mt < 4; mt++) {
                ldmx4(ah[mt], aH + (wm + mt * 16 + lrow) * A_STRIDE + kk + lcol);
                ldmx4(al[mt], aL + (wm + mt * 16 + lrow) * A_STRIDE + kk + lcol);
            }
#pragma unroll
            for (int ntp = 0; ntp < 2; ntp++) {
                ldmx4t(bh[ntp], bH + (kk + lrow) * B_STRIDE + wn + ntp * 16 + lcol);
                ldmx4t(bl[ntp], bL + (kk + lrow) * B_STRIDE + wn + ntp * 16 + lcol);
            }
#pragma unroll
            for (int mt = 0; mt < 4; mt++)
#pragma unroll
                for (int nt = 0; nt < 4; nt++) {
                    const int ntp = nt >> 1, off = (nt & 1) * 2;
                    mma16816(acc[mt][nt], ah[mt], bh[ntp][off], bh[ntp][off + 1]);
                    mma16816(acc[mt][nt], ah[mt], bl[ntp][off], bl[ntp][off + 1]);
                    mma16816(acc[mt][nt], al[mt], bh[ntp][off], bh[ntp][off + 1]);
                }
        }
        __syncthreads();
    }
#undef PREFETCH

    const int er = lane >> 2;
    const int ec = (lane & 3) * 2;
#pragma unroll
    for (int mt = 0; mt < 4; mt++)
#pragma unroll
        for (int nt = 0; nt < 4; nt++) {
            int r0 = m0 + wm + mt * 16 + er;
            int c0 = n0 + wn + nt * 8 + ec;
            float b0 = bias[c0], b1 = bias[c0 + 1];
            float v0 = acc[mt][nt][0] + b0, v1 = acc[mt][nt][1] + b1;
            float v2 = acc[mt][nt][2] + b0, v3 = acc[mt][nt][3] + b1;
            if (C) {
                *(float2*)(C + (size_t)r0 * N + c0) = make_float2(v0, v1);
                *(float2*)(C + (size_t)(r0 + 8) * N + c0) = make_float2(v2, v3);
            } else {
                __nv_bfloat16 h0 = __float2bfloat16(v0), h1 = __float2bfloat16(v1);
                __nv_bfloat16 h2 = __float2bfloat16(v2), h3 = __float2bfloat16(v3);
                *(__nv_bfloat162*)(Ch + (size_t)r0 * N + c0) = __nv_bfloat162(h0, h1);
                *(__nv_bfloat162*)(Ch + (size_t)(r0 + 8) * N + c0) = __nv_bfloat162(h2, h3);
                *(__nv_bfloat162*)(Cl + (size_t)r0 * N + c0) =
                    __nv_bfloat162(__float2bfloat16(v0 - __bfloat162float(h0)),
                                   __float2bfloat16(v1 - __bfloat162float(h1)));
                *(__nv_bfloat162*)(Cl + (size_t)(r0 + 8) * N + c0) =
                    __nv_bfloat162(__float2bfloat16(v2 - __bfloat162float(h2)),
                                   __float2bfloat16(v3 - __bfloat162float(h3)));
            }
        }
}

// ---------------------------------------------------------------------------
// Fused QKV GEMM launch: 768 CTAs (Q:512, K:128, V:128). V emits split bf16.
// ---------------------------------------------------------------------------
struct QKVArgs {
    const __nv_bfloat16 *xh, *xl, *yh, *yl;
    const __nv_bfloat16 *Wqh, *Wql, *Wkh, *Wkl, *Wvh, *Wvl;
    const float *bq, *bk, *bv;
    float *Q, *K;
    __nv_bfloat16 *Vh, *Vl;
};

__global__ __launch_bounds__(256) void qkv_gemm_kernel(QKVArgs a)
{
    extern __shared__ __nv_bfloat16 sm[];
    int bid = blockIdx.x;
    if (bid < 512) {
        gemm_tile(a.xh, a.xl, a.Wqh, a.Wql, a.bq,
                  a.Q, nullptr, nullptr,
                  D_MODEL, D_MODEL, (bid >> 5) * BM, (bid & 31) * BN, sm);
    } else if (bid < 640) {
        int t = bid - 512;
        gemm_tile(a.yh, a.yl, a.Wkh, a.Wkl, a.bk,
                  a.K, nullptr, nullptr,
                  GS_DIM, D_MODEL, (t >> 3) * BM, (t & 7) * BN, sm);
    } else {
        int t = bid - 640;
        gemm_tile(a.yh, a.yl, a.Wvh, a.Wvl, a.bv,
                  nullptr, a.Vh, a.Vl,
                  GS_DIM, D_MODEL, (t >> 3) * BM, (t & 7) * BN, sm);
    }
}

// Standalone GEMM (output projection), fp32 out
__global__ __launch_bounds__(256) void gemm_mma_kernel(
    const __nv_bfloat16* __restrict__ Ah, const __nv_bfloat16* __restrict__ Al,
    const __nv_bfloat16* __restrict__ Bh, const __nv_bfloat16* __restrict__ Bl,
    const float* __restrict__ bias, float* __restrict__ C, int N, int K)
{
    extern __shared__ __nv_bfloat16 sm[];
    gemm_tile(Ah, Al, Bh, Bl, bias, C, nullptr, nullptr,
              N, K, blockIdx.y * BM, blockIdx.x * BN, sm);
}

// ---------------------------------------------------------------------------
// RoPE: table, then fused apply+split
// ---------------------------------------------------------------------------
__global__ void rope_table_kernel()
{
    int idx = blockIdx.x * blockDim.x + threadIdx.x;
    if (idx >= S_LEN * GVS) return;
    int s = idx / GVS, i = idx % GVS;
    double phi = exp(-((double)i / (double)GVS) * log(5000.0));
    double sn, c;
    sincos((double)s * phi, &sn, &c);   // sin first, cos second
    g_tab[idx] = make_float2((float)c, (float)sn);
}

__global__ void rope_split_kernel(const float* __restrict__ T, int H,
                                  __nv_bfloat16* __restrict__ hi,
                                  __nv_bfloat16* __restrict__ lo, float scale)
{
    int idx = blockIdx.x * blockDim.x + threadIdx.x;
    int total = S_LEN * H * GVS;
    if (idx >= total) return;
    int i = idx % GVS;
    int h = (idx / GVS) % H;
    int s = idx / (GVS * H);
    float2 cs = g_tab[s * GVS + i];
    size_t base = ((size_t)s * H + h) * HEAD_DIM + 2 * i;
    float tr = T[base], ti = T[base + 1];
    float ro = (tr * cs.x - ti * cs.y) * scale;
    float io = (tr * cs.y + ti * cs.x) * scale;
    __nv_bfloat16 h0 = __float2bfloat16(ro);
    __nv_bfloat16 h1 = __float2bfloat16(io);
    hi[base]     = h0;
    hi[base + 1] = h1;
    lo[base]     = __float2bfloat16(ro - __bfloat162float(h0));
    lo[base + 1] = __float2bfloat16(io - __bfloat162float(h1));
}

// ---------------------------------------------------------------------------
// MMA flash attention (split bf16 in/out). Heavy q-tiles launch first.
// ---------------------------------------------------------------------------
#define QT 128
#define KT 64
#define DSTR 136
#define PSTR 72

__global__ __launch_bounds__(256) void attn_mma_kernel(
    const __nv_bfloat16* __restrict__ Qh, const __nv_bfloat16* __restrict__ Ql,
    const __nv_bfloat16* __restrict__ Kh, const __nv_bfloat16* __restrict__ Kl,
    const __nv_bfloat16* __restrict__ Vh, const __nv_bfloat16* __restrict__ Vl,
    __nv_bfloat16* __restrict__ Oh, __nv_bfloat16* __restrict__ Ol)
{
    extern __shared__ __nv_bfloat16 sb[];
    __nv_bfloat16* sQh = sb;
    __nv_bfloat16* sQl = sQh + QT * DSTR;
    __nv_bfloat16* sKh = sQl + QT * DSTR;
    __nv_bfloat16* sKl = sKh + KT * DSTR;
    __nv_bfloat16* sVh = sKl + KT * DSTR;
    __nv_bfloat16* sVl = sVh + KT * DSTR;
    __nv_bfloat16* sPh = sVl + KT * DSTR;
    __nv_bfloat16* sPl = sPh + QT * PSTR;

    const int tid  = threadIdx.x;
    const int lane = tid & 31;
    const int wid  = tid >> 5;
    const int wrow = wid * 16;
    const int qt   = (gridDim.x - 1) - blockIdx.x;   // heavy tiles first
    const int h    = blockIdx.y;
    const int q0   = qt * QT;
    const int kvh  = h >> 2;

    for (int t = tid; t < QT * 16; t += 256) {
        int r = t >> 4, c8 = (t & 15) * 8;
        const uint4* ph = (const uint4*)(Qh + (size_t)(q0 + r) * D_MODEL + h * HEAD_DIM + c8);
        const uint4* pl = (const uint4*)(Ql + (size_t)(q0 + r) * D_MODEL + h * HEAD_DIM + c8);
        *(uint4*)(sQh + r * DSTR + c8) = *ph;
        *(uint4*)(sQl + r * DSTR + c8) = *pl;
    }

    float oacc[16][4];
#pragma unroll
    for (int nt = 0; nt < 16; nt++)
#pragma unroll
        for (int v = 0; v < 4; v++) oacc[nt][v] = 0.0f;
    float m_lo = -1e30f, m_hi = -1e30f, l_lo = 0.0f, l_hi = 0.0f;

    const int lrow = lane & 15;
    const int lcol = (lane >> 4) * 8;
    const int er   = lane >> 2;
    const int ec   = (lane & 3) * 2;

    const int ktmax = 2 * qt + 1;
    for (int kt = 0; kt <= ktmax; kt++) {
        const int k0 = kt * KT;
        __syncthreads();
        for (int t = tid; t < KT * 16; t += 256) {
            int r = t >> 4, c8 = (t & 15) * 8;
            size_t g = (size_t)(k0 + r) * GS_DIM + kvh * HEAD_DIM + c8;
            *(uint4*)(sKh + r * DSTR + c8) = *(const uint4*)(Kh + g);
            *(uint4*)(sKl + r * DSTR + c8) = *(const uint4*)(Kl + g);
            *(uint4*)(sVh + r * DSTR + c8) = *(const uint4*)(Vh + g);
            *(uint4*)(sVl + r * DSTR + c8) = *(const uint4*)(Vl + g);
        }
        __syncthreads();

        if (k0 > q0 + wrow + 15) continue;

        float sacc[8][4];
#pragma unroll
        for (int nt = 0; nt < 8; nt++)
#pragma unroll
            for (int v = 0; v < 4; v++) sacc[nt][v] = 0.0f;

#pragma unroll
        for (int kk = 0; kk < 8; kk++) {
            uint32_t ah[4], al[4];
            ldmx4(ah, sQh + (wrow + lrow) * DSTR + kk * 16 + lcol);
            ldmx4(al, sQl + (wrow + lrow) * DSTR + kk * 16 + lcol);
#pragma unroll
            for (int np = 0; np < 4; np++) {
                uint32_t bh[4], bl[4];
                ldmx4(bh, sKh + (np * 16 + lrow) * DSTR + kk * 16 + lcol);
                ldmx4(bl, sKl + (np * 16 + lrow) * DSTR + kk * 16 + lcol);
                mma16816(sacc[2 * np],     ah, bh[0], bh[2]);
                mma16816(sacc[2 * np],     ah, bl[0], bl[2]);
                mma16816(sacc[2 * np],     al, bh[0], bh[2]);
                mma16816(sacc[2 * np + 1], ah, bh[1], bh[3]);
                mma16816(sacc[2 * np + 1], ah, bl[1], bl[3]);
                mma16816(sacc[2 * np + 1], al, bh[1], bh[3]);
            }
        }

        if (kt >= 2 * qt) {
            int gq_lo = q0 + wrow + er;
            int gq_hi = gq_lo + 8;
#pragma unroll
            for (int nt = 0; nt < 8; nt++) {
                int c0 = k0 + nt * 8 + ec;
                if (c0 > gq_lo)     sacc[nt][0] = -1e30f;
                if (c0 + 1 > gq_lo) sacc[nt][1] = -1e30f;
                if (c0 > gq_hi)     sacc[nt][2] = -1e30f;
                if (c0 + 1 > gq_hi) sacc[nt][3] = -1e30f;
            }
        }

        float mx_lo = -1e30f, mx_hi = -1e30f;
#pragma unroll
        for (int nt = 0; nt < 8; nt++) {
            mx_lo = fmaxf(mx_lo, fmaxf(sacc[nt][0], sacc[nt][1]));
            mx_hi = fmaxf(mx_hi, fmaxf(sacc[nt][2], sacc[nt][3]));
        }
        mx_lo = fmaxf(mx_lo, __shfl_xor_sync(0xffffffffu, mx_lo, 1));
        mx_lo = fmaxf(mx_lo, __shfl_xor_sync(0xffffffffu, mx_lo, 2));
        mx_hi = fmaxf(mx_hi, __shfl_xor_sync(0xffffffffu, mx_hi, 1));
        mx_hi = fmaxf(mx_hi, __shfl_xor_sync(0xffffffffu, mx_hi, 2));

        float mn_lo = fmaxf(m_lo, mx_lo);
        float mn_hi = fmaxf(m_hi, mx_hi);
        float al_lo = __expf(m_lo - mn_lo);
        float al_hi = __expf(m_hi - mn_hi);

        float sum_lo = 0.0f, sum_hi = 0.0f;
#pragma unroll
        for (int nt = 0; nt < 8; nt++) {
            float p0 = __expf(sacc[nt][0] - mn_lo);
            float p1 = __expf(sacc[nt][1] - mn_lo);
            float p2 = __expf(sacc[nt][2] - mn_hi);
            float p3 = __expf(sacc[nt][3] - mn_hi);
            sum_lo += p0 + p1;
            sum_hi += p2 + p3;
            int c = nt * 8 + ec;
            __nv_bfloat16 h0 = __float2bfloat16(p0);
            __nv_bfloat16 h1 = __float2bfloat16(p1);
            __nv_bfloat16 h2 = __float2bfloat16(p2);
            __nv_bfloat16 h3 = __float2bfloat16(p3);
            sPh[(wrow + er) * PSTR + c]     = h0;
            sPh[(wrow + er) * PSTR + c + 1] = h1;
            sPh[(wrow + er + 8) * PSTR + c]     = h2;
            sPh[(wrow + er + 8) * PSTR + c + 1] = h3;
            sPl[(wrow + er) * PSTR + c]     = __float2bfloat16(p0 - __bfloat162float(h0));
            sPl[(wrow + er) * PSTR + c + 1] = __float2bfloat16(p1 - __bfloat162float(h1));
            sPl[(wrow + er + 8) * PSTR + c]     = __float2bfloat16(p2 - __bfloat162float(h2));
            sPl[(wrow + er + 8) * PSTR + c + 1] = __float2bfloat16(p3 - __bfloat162float(h3));
        }
        sum_lo += __shfl_xor_sync(0xffffffffu, sum_lo, 1);
        sum_lo += __shfl_xor_sync(0xffffffffu, sum_lo, 2);
        sum_hi += __shfl_xor_sync(0xffffffffu, sum_hi, 1);
        sum_hi += __shfl_xor_sync(0xffffffffu, sum_hi, 2);

        l_lo = l_lo * al_lo + sum_lo;
        l_hi = l_hi * al_hi + sum_hi;
        m_lo = mn_lo; m_hi = mn_hi;

#pragma unroll
        for (int nt = 0; nt < 16; nt++) {
            oacc[nt][0] *= al_lo; oacc[nt][1] *= al_lo;
            oacc[nt][2] *= al_hi; oacc[nt][3] *= al_hi;
        }
        __syncwarp();

#pragma unroll
        for (int kk = 0; kk < 4; kk++) {
            uint32_t ah[4], al2[4];
            ldmx4(ah,  sPh + (wrow + lrow) * PSTR + kk * 16 + lcol);
            ldmx4(al2, sPl + (wrow + lrow) * PSTR + kk * 16 + lcol);
#pragma unroll
            for (int np = 0; np < 8; np++) {
                uint32_t bh[4], bl[4];
                ldmx4t(bh, sVh + (kk * 16 + lrow) * DSTR + np * 16 + lcol);
                ldmx4t(bl, sVl + (kk * 16 + lrow) * DSTR + np * 16 + lcol);
                mma16816(oacc[2 * np],     ah,  bh[0], bh[1]);
                mma16816(oacc[2 * np],     al2, bh[0], bh[1]);
                mma16816(oacc[2 * np],     ah,  bl[0], bl[1]);
                mma16816(oacc[2 * np + 1], ah,  bh[2], bh[3]);
                mma16816(oacc[2 * np + 1], al2, bh[2], bh[3]);
                mma16816(oacc[2 * np + 1], ah,  bl[2], bl[3]);
            }
        }
    }

    float inv_lo = 1.0f / l_lo;
    float inv_hi = 1.0f / l_hi;
    int gq_lo = q0 + wrow + er;
#pragma unroll
    for (int nt = 0; nt < 16; nt++) {
        int c = h * HEAD_DIM + nt * 8 + ec;
        float v0 = oacc[nt][0] * inv_lo, v1 = oacc[nt][1] * inv_lo;
        float v2 = oacc[nt][2] * inv_hi, v3 = oacc[nt][3] * inv_hi;
        __nv_bfloat16 h0 = __float2bfloat16(v0), h1 = __float2bfloat16(v1);
        __nv_bfloat16 h2 = __float2bfloat16(v2), h3 = __float2bfloat16(v3);
        __nv_bfloat162* p;
        p = (__nv_bfloat162*)(Oh + (size_t)gq_lo * D_MODEL + c);
        *p = __nv_bfloat162(h0, h1);
        p = (__nv_bfloat162*)(Oh + (size_t)(gq_lo + 8) * D_MODEL + c);
        *p = __nv_bfloat162(h2, h3);
        p = (__nv_bfloat162*)(Ol + (size_t)gq_lo * D_MODEL + c);
        *p = __nv_bfloat162(__float2bfloat16(v0 - __bfloat162float(h0)),
                            __float2bfloat16(v1 - __bfloat162float(h1)));
        p = (__nv_bfloat162*)(Ol + (size_t)(gq_lo + 8) * D_MODEL + c);
        *p = __nv_bfloat162(__float2bfloat16(v2 - __bfloat162float(h2)),
                            __float2bfloat16(v3 - __bfloat162float(h3)));
    }
}

// ---------------------------------------------------------------------------
// Launch. Input order (R6-confirmed dict order):
//   0:x 1:y 2:Wq 3:bq 4:Wk 5:bk 6:Wv 7:bv 8:Wo 9:bo
// ---------------------------------------------------------------------------
extern "C" void kernel_launch(void* const* d_in, const int* in_sizes, int n_in,
                              void* d_out, int out_size)
{
    (void)in_sizes; (void)n_in; (void)out_size;
    const float* x  = (const float*)d_in[0];
    const float* y  = (const float*)d_in[1];
    const float* Wq = (const float*)d_in[2];
    const float* bq = (const float*)d_in[3];
    const float* Wk = (const float*)d_in[4];
    const float* bk = (const float*)d_in[5];
    const float* Wv = (const float*)d_in[6];
    const float* bv = (const float*)d_in[7];
    const float* Wo = (const float*)d_in[8];
    const float* bo = (const float*)d_in[9];
    float* out = (float*)d_out;

    float *Qb, *Kb;
    cudaGetSymbolAddress((void**)&Qb, g_Q);
    cudaGetSymbolAddress((void**)&Kb, g_K);

    __nv_bfloat16 *xh, *xl, *yh, *yl, *Wqh, *Wql, *Wkh, *Wkl, *Wvh, *Wvl,
                  *Woh, *Wol, *AOh, *AOl, *Qsh, *Qsl, *Ksh, *Ksl, *Vsh, *Vsl;
    cudaGetSymbolAddress((void**)&xh, g_xh);   cudaGetSymbolAddress((void**)&xl, g_xl);
    cudaGetSymbolAddress((void**)&yh, g_yh);   cudaGetSymbolAddress((void**)&yl, g_yl);
    cudaGetSymbolAddress((void**)&Wqh, g_Wqh); cudaGetSymbolAddress((void**)&Wql, g_Wql);
    cudaGetSymbolAddress((void**)&Wkh, g_Wkh); cudaGetSymbolAddress((void**)&Wkl, g_Wkl);
    cudaGetSymbolAddress((void**)&Wvh, g_Wvh); cudaGetSymbolAddress((void**)&Wvl, g_Wvl);
    cudaGetSymbolAddress((void**)&Woh, g_Woh); cudaGetSymbolAddress((void**)&Wol, g_Wol);
    cudaGetSymbolAddress((void**)&AOh, g_AOh); cudaGetSymbolAddress((void**)&AOl, g_AOl);
    cudaGetSymbolAddress((void**)&Qsh, g_Qh);  cudaGetSymbolAddress((void**)&Qsl, g_Ql);
    cudaGetSymbolAddress((void**)&Ksh, g_Kh);  cudaGetSymbolAddress((void**)&Ksl, g_Kl);
    cudaGetSymbolAddress((void**)&Vsh, g_Vh);  cudaGetSymbolAddress((void**)&Vsl, g_Vl);

    cudaFuncSetAttribute(qkv_gemm_kernel, cudaFuncAttributeMaxDynamicSharedMemorySize, GEMM_SMEM);
    cudaFuncSetAttribute(gemm_mma_kernel, cudaFuncAttributeMaxDynamicSharedMemorySize, GEMM_SMEM);
    const int smem_attn = (2 * QT * DSTR + 4 * KT * DSTR + 2 * QT * PSTR) * 2;
    cudaFuncSetAttribute(attn_mma_kernel, cudaFuncAttributeMaxDynamicSharedMemorySize, smem_attn);

    // RoPE table (independent)
    rope_table_kernel<<<(S_LEN * GVS + 255) / 256, 256>>>();

    // Mega-split: x, y, Wq, Wk, Wv, Wo in one launch
    {
        SplitArgs a;
        const float* srcs[6] = {x, y, Wq, Wk, Wv, Wo};
        __nv_bfloat16* his[6] = {xh, yh, Wqh, Wkh, Wvh, Woh};
        __nv_bfloat16* los[6] = {xl, yl, Wql, Wkl, Wvl, Wol};
        int ns[6] = {S_LEN * D_MODEL, S_LEN * D_MODEL,
                     D_MODEL * D_MODEL, D_MODEL * GS_DIM,
                     D_MODEL * GS_DIM, D_MODEL * D_MODEL};
        int acc = 0;
        for (int i = 0; i < 6; i++) {
            a.src[i] = srcs[i]; a.hi[i] = his[i]; a.lo[i] = los[i];
            a.off[i] = acc; acc += ns[i];
        }
        a.off[6] = acc;
        mega_split_kernel<<<(acc + 255) / 256, 256>>>(a);
    }

    // Fused QKV projection (768 CTAs; V emits split bf16 directly)
    {
        QKVArgs a;
        a.xh = xh; a.xl = xl; a.yh = yh; a.yl = yl;
        a.Wqh = Wqh; a.Wql = Wql; a.Wkh = Wkh; a.Wkl = Wkl; a.Wvh = Wvh; a.Wvl = Wvl;
        a.bq = bq; a.bk = bk; a.bv = bv;
        a.Q = Qb; a.K = Kb; a.Vh = Vsh; a.Vl = Vsl;
        qkv_gemm_kernel<<<768, 256, GEMM_SMEM>>>(a);
    }

    // RoPE + split (Q gets softmax scale folded)
    rope_split_kernel<<<(S_LEN * N_HEAD * GVS + 255) / 256, 256>>>(
        Qb, N_HEAD, Qsh, Qsl, 0.08838834764831845f);
    rope_split_kernel<<<(S_LEN * KV_HEAD * GVS + 255) / 256, 256>>>(
        Kb, KV_HEAD, Ksh, Ksl, 1.0f);

    // MMA flash attention -> split bf16 AO
    attn_mma_kernel<<<dim3(S_LEN / QT, N_HEAD), 256, smem_attn>>>(
        Qsh, Qsl, Ksh, Ksl, Vsh, Vsl, AOh, AOl);

    // Output projection
    gemm_mma_kernel<<<dim3(D_MODEL / BN, S_LEN / BM), 256, GEMM_SMEM>>>(
        AOh, AOl, Woh, Wol, bo, out, D_MODEL, D_MODEL);
}